// round 5
// baseline (speedup 1.0000x reference)
#include <cuda_runtime.h>
#include <stdint.h>

#define EDGE_IN 19
#define WIDTH   64
#define NODE_IN 16
#define OUT     16
#define N_NODES_MAX 50000
#define T 384      // threads per block
#define NBLK 148   // persistent blocks (~1 per SM)

// ---- shared memory layout (floats) ----
#define S_W0 0
#define S_B0 (S_W0 + EDGE_IN*WIDTH)        // 1216
#define S_W1 (S_B0 + WIDTH)                // 1280
#define S_B1 (S_W1 + WIDTH*WIDTH)          // 5376
#define S_W2 (S_B1 + WIDTH)                // 5440
#define S_B2 (S_W2 + WIDTH*WIDTH)          // 9536
#define S_LW (S_B2 + WIDTH)                // 9600
#define S_LB (S_LW + WIDTH*NODE_IN*OUT)    // 25984
#define S_ACT (S_LB + NODE_IN*OUT)         // 26240
#define SMEM_FLOATS (S_ACT + WIDTH*T)      // 50816
#define SMEM_BYTES (SMEM_FLOATS*4)         // 203264

typedef unsigned long long u64;

// Packed dual-fp32 FMA (Blackwell f32x2 path; ptxas never emits this from C++)
__device__ __forceinline__ u64 ffma2(u64 a, u64 b, u64 c) {
    u64 d;
    asm("fma.rn.f32x2 %0, %1, %2, %3;" : "=l"(d) : "l"(a), "l"(b), "l"(c));
    return d;
}
__device__ __forceinline__ u64 pack2(float x) {
    u64 r;
    asm("mov.b64 %0, {%1, %1};" : "=l"(r) : "f"(x));
    return r;
}
__device__ __forceinline__ void unpack2(u64 v, float& lo, float& hi) {
    asm("mov.b64 {%0, %1}, %2;" : "=f"(lo), "=f"(hi) : "l"(v));
}
// monotone float->int ordering map (branch-free scatter-max via RED.MAX.S32)
__device__ __forceinline__ int ford(float f) {
    int b = __float_as_int(f);
    return b >= 0 ? b : (b ^ 0x7fffffff);
}

// scatter-max accumulator in ordered-int space; init = INT_MIN (below any float)
__device__ int g_agg[N_NODES_MAX * OUT];

__global__ void init_agg_kernel(int n) {
    int i = blockIdx.x * blockDim.x + threadIdx.x;
    if (i < n) g_agg[i] = (int)0x80000000;
}

__global__ __launch_bounds__(T, 1)
void edge_kernel(const float* __restrict__ node_feats,
                 const int*   __restrict__ edge_index,
                 const float* __restrict__ edge_feats,
                 const float* __restrict__ w0, const float* __restrict__ b0,
                 const float* __restrict__ w1, const float* __restrict__ b1,
                 const float* __restrict__ w2, const float* __restrict__ b2,
                 const float* __restrict__ lw, const float* __restrict__ lb,
                 int E)
{
    extern __shared__ float s[];
    const int tid = threadIdx.x;

    // ---- cooperative weight load into smem (once per persistent block) ----
    {
        float4* d = (float4*)s;
        const float4* v;
        v = (const float4*)w0; for (int i = tid; i < (EDGE_IN*WIDTH)/4; i += T) d[S_W0/4 + i] = v[i];
        v = (const float4*)b0; for (int i = tid; i < WIDTH/4;          i += T) d[S_B0/4 + i] = v[i];
        v = (const float4*)w1; for (int i = tid; i < (WIDTH*WIDTH)/4;  i += T) d[S_W1/4 + i] = v[i];
        v = (const float4*)b1; for (int i = tid; i < WIDTH/4;          i += T) d[S_B1/4 + i] = v[i];
        v = (const float4*)w2; for (int i = tid; i < (WIDTH*WIDTH)/4;  i += T) d[S_W2/4 + i] = v[i];
        v = (const float4*)b2; for (int i = tid; i < WIDTH/4;          i += T) d[S_B2/4 + i] = v[i];
        v = (const float4*)lw; for (int i = tid; i < (WIDTH*NODE_IN*OUT)/4; i += T) d[S_LW/4 + i] = v[i];
        v = (const float4*)lb; for (int i = tid; i < (NODE_IN*OUT)/4;  i += T) d[S_LB/4 + i] = v[i];
    }
    __syncthreads();

    float* act = s + S_ACT;   // per-thread column: act[row*T + tid]
    const int ntiles = (E + T - 1) / T;

    for (int tile = blockIdx.x; tile < ntiles; tile += gridDim.x) {
        int e = tile * T + tid;
        bool valid = (e < E);
        int ee = valid ? e : (E - 1);

        // stage this edge's features in own smem column
        #pragma unroll
        for (int k = 0; k < EDGE_IN; k++)
            act[k * T + tid] = edge_feats[(size_t)ee * EDGE_IN + k];

        u64 h2[WIDTH/2];

        // ---- MLP layer macro: K inputs (in act rows) -> 64 outputs, relu, back to act ----
        #define LAYER(K, SW, SB)                                                     \
        {                                                                            \
            const u64* __restrict__ bb = (const u64*)(s + (SB));                     \
            _Pragma("unroll")                                                        \
            for (int j = 0; j < WIDTH/2; j++) h2[j] = bb[j];                         \
            _Pragma("unroll 1")                                                      \
            for (int k = 0; k < (K); k++) {                                          \
                u64 x = pack2(act[k * T + tid]);                                     \
                const ulonglong2* __restrict__ wr =                                  \
                    (const ulonglong2*)(s + (SW) + k * WIDTH);                       \
                _Pragma("unroll")                                                    \
                for (int j = 0; j < WIDTH/4; j++) {                                  \
                    ulonglong2 w = wr[j];                                            \
                    h2[2*j+0] = ffma2(x, w.x, h2[2*j+0]);                            \
                    h2[2*j+1] = ffma2(x, w.y, h2[2*j+1]);                            \
                }                                                                    \
            }                                                                        \
            _Pragma("unroll")                                                        \
            for (int j = 0; j < WIDTH/2; j++) {                                      \
                float lo, hi; unpack2(h2[j], lo, hi);                                \
                act[(2*j+0) * T + tid] = fmaxf(lo, 0.f);                             \
                act[(2*j+1) * T + tid] = fmaxf(hi, 0.f);                             \
            }                                                                        \
        }

        LAYER(EDGE_IN, S_W0, S_B0)
        LAYER(WIDTH,   S_W1, S_B1)
        LAYER(WIDTH,   S_W2, S_B2)
        #undef LAYER
        // act rows now hold h2 (post layer-2 relu)

        // ---- fused (h2 @ lin_w + lin_b) contracted with src node feats ----
        int srcn = edge_index[ee];
        int dstn = edge_index[E + ee];

        u64 xp[NODE_IN];
        {
            const float4* nf = (const float4*)(node_feats + (size_t)srcn * NODE_IN);
            float4 a = nf[0], b = nf[1], c = nf[2], d4 = nf[3];
            xp[0]=pack2(a.x);  xp[1]=pack2(a.y);  xp[2]=pack2(a.z);  xp[3]=pack2(a.w);
            xp[4]=pack2(b.x);  xp[5]=pack2(b.y);  xp[6]=pack2(b.z);  xp[7]=pack2(b.w);
            xp[8]=pack2(c.x);  xp[9]=pack2(c.y);  xp[10]=pack2(c.z); xp[11]=pack2(c.w);
            xp[12]=pack2(d4.x);xp[13]=pack2(d4.y);xp[14]=pack2(d4.z);xp[15]=pack2(d4.w);
        }

        // bias part: msg[o] = sum_i x_i * lb[i,o]
        u64 msg2[OUT/2];
        {
            #pragma unroll
            for (int o = 0; o < OUT/2; o++) msg2[o] = 0ull;
            const ulonglong2* __restrict__ lbv = (const ulonglong2*)(s + S_LB);
            #pragma unroll
            for (int i = 0; i < NODE_IN; i++) {
                #pragma unroll
                for (int o4 = 0; o4 < OUT/4; o4++) {
                    ulonglong2 w = lbv[i * (OUT/4) + o4];
                    msg2[2*o4+0] = ffma2(xp[i], w.x, msg2[2*o4+0]);
                    msg2[2*o4+1] = ffma2(xp[i], w.y, msg2[2*o4+1]);
                }
            }
        }

        // k-outer: t[o] = sum_i x_i*lw[k,i,o]; msg[o] += h_k*t[o]
        const ulonglong2* __restrict__ lwv = (const ulonglong2*)(s + S_LW);
        #pragma unroll 1
        for (int k = 0; k < WIDTH; k++) {
            u64 hp = pack2(act[k * T + tid]);
            u64 t2[OUT/2];
            #pragma unroll
            for (int o = 0; o < OUT/2; o++) t2[o] = 0ull;
            const ulonglong2* __restrict__ lwk = lwv + k * (NODE_IN*OUT/4);
            #pragma unroll
            for (int i = 0; i < NODE_IN; i++) {
                #pragma unroll
                for (int o4 = 0; o4 < OUT/4; o4++) {
                    ulonglong2 w = lwk[i * (OUT/4) + o4];
                    t2[2*o4+0] = ffma2(xp[i], w.x, t2[2*o4+0]);
                    t2[2*o4+1] = ffma2(xp[i], w.y, t2[2*o4+1]);
                }
            }
            #pragma unroll
            for (int o = 0; o < OUT/2; o++) msg2[o] = ffma2(hp, t2[o], msg2[o]);
        }

        // ---- scatter max: branch-free ordered-int RED.MAX ----
        if (valid) {
            int* slot = &g_agg[(size_t)dstn * OUT];
            #pragma unroll
            for (int o = 0; o < OUT/2; o++) {
                float lo, hi; unpack2(msg2[o], lo, hi);
                atomicMax(slot + 2*o + 0, ford(lo));
                atomicMax(slot + 2*o + 1, ford(hi));
            }
        }
    }
}

__global__ __launch_bounds__(256)
void node_kernel(const float* __restrict__ node_feats,
                 const float* __restrict__ root_w,
                 const float* __restrict__ bias,
                 float* __restrict__ out, int N)
{
    __shared__ float rw[NODE_IN * OUT];
    __shared__ float bs[OUT];
    int tid = threadIdx.x;
    if (tid < NODE_IN * OUT) rw[tid] = root_w[tid];
    if (tid < OUT) bs[tid] = bias[tid];
    __syncthreads();

    int n = blockIdx.x * 256 + tid;
    if (n >= N) return;

    float xi[NODE_IN];
    {
        const float4* nf = (const float4*)(node_feats + (size_t)n * NODE_IN);
        float4 a = nf[0], b = nf[1], c = nf[2], d4 = nf[3];
        xi[0]=a.x;  xi[1]=a.y;  xi[2]=a.z;  xi[3]=a.w;
        xi[4]=b.x;  xi[5]=b.y;  xi[6]=b.z;  xi[7]=b.w;
        xi[8]=c.x;  xi[9]=c.y;  xi[10]=c.z; xi[11]=c.w;
        xi[12]=d4.x; xi[13]=d4.y; xi[14]=d4.z; xi[15]=d4.w;
    }

    float o[OUT];
    #pragma unroll
    for (int j = 0; j < OUT; j++) o[j] = bs[j];
    #pragma unroll
    for (int i = 0; i < NODE_IN; i++) {
        float xv = xi[i];
        #pragma unroll
        for (int j = 0; j < OUT; j++) o[j] = fmaf(xv, rw[i*OUT + j], o[j]);
    }

    #pragma unroll
    for (int j = 0; j < OUT; j++) {
        int a = g_agg[(size_t)n * OUT + j];
        float av;
        if (a == (int)0x80000000) av = 0.f;                 // no in-edges
        else av = __int_as_float(a >= 0 ? a : (a ^ 0x7fffffff));
        o[j] += av;
    }

    float4* ov = (float4*)(out + (size_t)n * OUT);
    ov[0] = make_float4(o[0],  o[1],  o[2],  o[3]);
    ov[1] = make_float4(o[4],  o[5],  o[6],  o[7]);
    ov[2] = make_float4(o[8],  o[9],  o[10], o[11]);
    ov[3] = make_float4(o[12], o[13], o[14], o[15]);
}

extern "C" void kernel_launch(void* const* d_in, const int* in_sizes, int n_in,
                              void* d_out, int out_size)
{
    const float* node_feats = (const float*)d_in[0];
    const int*   edge_index = (const int*)  d_in[1];
    const float* edge_feats = (const float*)d_in[2];
    const float* w0 = (const float*)d_in[3];
    const float* b0 = (const float*)d_in[4];
    const float* w1 = (const float*)d_in[5];
    const float* b1 = (const float*)d_in[6];
    const float* w2 = (const float*)d_in[7];
    const float* b2 = (const float*)d_in[8];
    const float* lw = (const float*)d_in[9];
    const float* lb = (const float*)d_in[10];
    const float* root_w = (const float*)d_in[11];
    const float* bias   = (const float*)d_in[12];

    int E = in_sizes[1] / 2;
    int N = in_sizes[0] / NODE_IN;

    cudaFuncSetAttribute(edge_kernel, cudaFuncAttributeMaxDynamicSharedMemorySize, SMEM_BYTES);

    init_agg_kernel<<<(N * OUT + 255) / 256, 256>>>(N * OUT);

    int ntiles = (E + T - 1) / T;
    int grid = ntiles < NBLK ? ntiles : NBLK;
    edge_kernel<<<grid, T, SMEM_BYTES>>>(
        node_feats, edge_index, edge_feats, w0, b0, w1, b1, w2, b2, lw, lb, E);

    node_kernel<<<(N + 255) / 256, 256>>>(node_feats, root_w, bias, (float*)d_out, N);
}

// round 6
// speedup vs baseline: 1.4815x; 1.4815x over previous
#include <cuda_runtime.h>
#include <cuda_bf16.h>
#include <stdint.h>

#define EDGE_IN 19
#define WIDTH   64
#define NODE_IN 16
#define OUT     16
#define N_NODES_MAX 50000
#define T 256        // threads per block = edges per tile (32 per warp)
#define ACT_S 264    // act row stride: ==8 mod 32 -> conflict-free A-frag gather
#define XS_S 20      // x staging row stride
#define NBLK 148

// ---- shared memory layout (float offsets) ----
#define S_W0   0
#define S_B0   1216
#define S_W1   1280
#define S_B1   5376
#define S_W2   5440
#define S_B2   9536
#define S_LB   9600
#define S_LWHI 9856                    // 16384 floats: tf32-hi, B-frag permuted
#define S_LWLO 26240                   // 8192 floats (16384 bf16 lo residuals)
#define S_XS   34432                   // 256*20
#define S_ACT  39552                   // 64*264
#define SMEM_FLOATS 56448
#define SMEM_BYTES (SMEM_FLOATS*4)     // 225792 B

typedef unsigned long long u64;

__device__ __forceinline__ u64 ffma2(u64 a, u64 b, u64 c) {
    u64 d; asm("fma.rn.f32x2 %0, %1, %2, %3;" : "=l"(d) : "l"(a), "l"(b), "l"(c)); return d;
}
__device__ __forceinline__ u64 pack2(float x) {
    u64 r; asm("mov.b64 %0, {%1, %1};" : "=l"(r) : "f"(x)); return r;
}
__device__ __forceinline__ u64 packf(float lo, float hi) {
    u64 r; asm("mov.b64 %0, {%1, %2};" : "=l"(r) : "f"(lo), "f"(hi)); return r;
}
__device__ __forceinline__ void unpack2(u64 v, float& lo, float& hi) {
    asm("mov.b64 {%0, %1}, %2;" : "=f"(lo), "=f"(hi) : "l"(v));
}
__device__ __forceinline__ int ford(float f) {
    int b = __float_as_int(f); return b >= 0 ? b : (b ^ 0x7fffffff);
}
__device__ __forceinline__ unsigned tf32_of(float x) {
    unsigned r; asm("cvt.rna.tf32.f32 %0, %1;" : "=r"(r) : "f"(x)); return r;
}
__device__ __forceinline__ void mma8(float* d, const unsigned* a, unsigned b0, unsigned b1) {
    asm volatile("mma.sync.aligned.m16n8k8.row.col.f32.tf32.tf32.f32 "
        "{%0,%1,%2,%3}, {%4,%5,%6,%7}, {%8,%9}, {%0,%1,%2,%3};"
        : "+f"(d[0]), "+f"(d[1]), "+f"(d[2]), "+f"(d[3])
        : "r"(a[0]), "r"(a[1]), "r"(a[2]), "r"(a[3]), "r"(b0), "r"(b1));
}

__device__ int g_agg[N_NODES_MAX * OUT];
__device__ float g_lwhi[WIDTH * NODE_IN * OUT];
__device__ __nv_bfloat16 g_lwlo[WIDTH * NODE_IN * OUT];

__global__ void init_agg_kernel(int n) {
    int i = blockIdx.x * blockDim.x + threadIdx.x;
    if (i < n) g_agg[i] = (int)0x80000000;
}

// Split lin_w into tf32-hi + bf16-lo, permuted into m16n8k8 B-fragment order.
// Value (k,n): tile (ks=k/8, nt=n/8); thread t=(n%8)*4 + (k%4); slot=(k%8)/4.
__global__ void prep_lw_kernel(const float* __restrict__ lw) {
    int idx = blockIdx.x * 256 + threadIdx.x;
    if (idx >= WIDTH * NODE_IN * OUT) return;
    int k = idx >> 8, nn = idx & 255;
    float w = lw[idx];
    float hif = __uint_as_float(tf32_of(w));
    int ks = k >> 3, kin = k & 7, slot = kin >> 2, kq = kin & 3;
    int pos = ((ks * 32 + (nn >> 3)) * 32 + (nn & 7) * 4 + kq) * 2 + slot;
    g_lwhi[pos] = hif;
    g_lwlo[pos] = __float2bfloat16(w - hif);
}

__global__ __launch_bounds__(T, 1)
void edge_kernel(const float* __restrict__ node_feats,
                 const int*   __restrict__ edge_index,
                 const float* __restrict__ edge_feats,
                 const float* __restrict__ w0, const float* __restrict__ b0,
                 const float* __restrict__ w1, const float* __restrict__ b1,
                 const float* __restrict__ w2, const float* __restrict__ b2,
                 const float* __restrict__ lb, int E)
{
    extern __shared__ float s[];
    const int tid = threadIdx.x;
    const int lane = tid & 31, wid = tid >> 5;
    const int g = lane >> 2, tig = lane & 3;

    { // cooperative weight load (once per persistent block)
        float4* d = (float4*)s; const float4* v;
        v = (const float4*)w0;     for (int i = tid; i < (EDGE_IN*WIDTH)/4;      i += T) d[S_W0/4 + i] = v[i];
        v = (const float4*)b0;     for (int i = tid; i < WIDTH/4;                i += T) d[S_B0/4 + i] = v[i];
        v = (const float4*)w1;     for (int i = tid; i < (WIDTH*WIDTH)/4;        i += T) d[S_W1/4 + i] = v[i];
        v = (const float4*)b1;     for (int i = tid; i < WIDTH/4;                i += T) d[S_B1/4 + i] = v[i];
        v = (const float4*)w2;     for (int i = tid; i < (WIDTH*WIDTH)/4;        i += T) d[S_W2/4 + i] = v[i];
        v = (const float4*)b2;     for (int i = tid; i < WIDTH/4;                i += T) d[S_B2/4 + i] = v[i];
        v = (const float4*)lb;     for (int i = tid; i < (NODE_IN*OUT)/4;        i += T) d[S_LB/4 + i] = v[i];
        v = (const float4*)g_lwhi; for (int i = tid; i < (WIDTH*NODE_IN*OUT)/4;  i += T) d[S_LWHI/4 + i] = v[i];
        v = (const float4*)g_lwlo; for (int i = tid; i < (WIDTH*NODE_IN*OUT)/8;  i += T) d[S_LWLO/4 + i] = v[i];
    }
    __syncthreads();

    float* act = s + S_ACT;
    const int ntiles = (E + T - 1) / T;

    for (int tile = blockIdx.x; tile < ntiles; tile += gridDim.x) {
        int e = tile * T + tid;
        int ee = (e < E) ? e : (E - 1);

        #pragma unroll
        for (int k = 0; k < EDGE_IN; k++)
            act[k * ACT_S + tid] = edge_feats[(size_t)ee * EDGE_IN + k];

        u64 h2[WIDTH/2];
        #define LAYER(K, SW, SB)                                                     \
        {                                                                            \
            const u64* __restrict__ bb = (const u64*)(s + (SB));                     \
            _Pragma("unroll")                                                        \
            for (int j = 0; j < WIDTH/2; j++) h2[j] = bb[j];                         \
            _Pragma("unroll 1")                                                      \
            for (int k = 0; k < (K); k++) {                                          \
                u64 x = pack2(act[k * ACT_S + tid]);                                 \
                const ulonglong2* __restrict__ wr =                                  \
                    (const ulonglong2*)(s + (SW) + k * WIDTH);                       \
                _Pragma("unroll")                                                    \
                for (int j = 0; j < WIDTH/4; j++) {                                  \
                    ulonglong2 w = wr[j];                                            \
                    h2[2*j+0] = ffma2(x, w.x, h2[2*j+0]);                            \
                    h2[2*j+1] = ffma2(x, w.y, h2[2*j+1]);                            \
                }                                                                    \
            }                                                                        \
            _Pragma("unroll")                                                        \
            for (int j = 0; j < WIDTH/2; j++) {                                      \
                float lo, hi; unpack2(h2[j], lo, hi);                                \
                act[(2*j+0) * ACT_S + tid] = fmaxf(lo, 0.f);                         \
                act[(2*j+1) * ACT_S + tid] = fmaxf(hi, 0.f);                         \
            }                                                                        \
        }
        LAYER(EDGE_IN, S_W0, S_B0)
        LAYER(WIDTH,   S_W1, S_B1)
        LAYER(WIDTH,   S_W2, S_B2)
        #undef LAYER

        { // stage src node feats (row per edge)
            const float4* nf = (const float4*)(node_feats + (size_t)edge_index[ee] * NODE_IN);
            float4* xr = (float4*)(s + S_XS + tid * XS_S);
            xr[0] = nf[0]; xr[1] = nf[1]; xr[2] = nf[2]; xr[3] = nf[3];
        }
        __syncwarp();

        // resident A fragments: a[q]: row g+(q&1)*8, col tig+(q>>1)*4
        unsigned Ah[2][8][4], Al[2][8][4];
        #pragma unroll
        for (int mt = 0; mt < 2; mt++)
            #pragma unroll
            for (int ks = 0; ks < 8; ks++)
                #pragma unroll
                for (int q = 0; q < 4; q++) {
                    int el = 32*wid + 16*mt + g + (q & 1) * 8;
                    int kk = 8*ks + tig + (q >> 1) * 4;
                    float v = act[kk * ACT_S + el];
                    unsigned hu = tf32_of(v);
                    Ah[mt][ks][q] = hu;
                    Al[mt][ks][q] = tf32_of(v - __uint_as_float(hu));
                }

        // msg accumulators: 4 edges x (2 u64 = 4 outputs {2tig,2tig+1,2tig+8,2tig+9})
        u64 msg[4][2];
        #pragma unroll
        for (int j = 0; j < 4; j++) { msg[j][0] = 0ull; msg[j][1] = 0ull; }
        // bias part: sum_i x_i * lb[i, o]
        #pragma unroll 1
        for (int i = 0; i < NODE_IN; i++) {
            u64 lb0 = *(const u64*)(s + S_LB + i*OUT + 2*tig);
            u64 lb1 = *(const u64*)(s + S_LB + i*OUT + 2*tig + 8);
            #pragma unroll
            for (int j = 0; j < 4; j++) {
                int el = 32*wid + (j >> 1) * 16 + (j & 1) * 8 + g;
                u64 xv = pack2(s[S_XS + el * XS_S + i]);
                msg[j][0] = ffma2(xv, lb0, msg[j][0]);
                msg[j][1] = ffma2(xv, lb1, msg[j][1]);
            }
        }

        // GEMM T = H2 @ LW fused with x-contraction, nt-outer / ks-inner
        #pragma unroll 1
        for (int nt = 0; nt < 32; nt++) {
            float d[2][4] = {{0,0,0,0},{0,0,0,0}};
            #pragma unroll
            for (int ks = 0; ks < 8; ks++) {
                int fidx = (ks * 32 + nt) * 32 + lane;
                u64 bh = *(const u64*)(s + S_LWHI + fidx * 2);
                float bh0, bh1; unpack2(bh, bh0, bh1);
                unsigned blo = *(const unsigned*)(s + S_LWLO + fidx);
                unsigned b0h = __float_as_uint(bh0), b1h = __float_as_uint(bh1);
                unsigned b0l = blo << 16, b1l = blo & 0xffff0000u;
                #pragma unroll
                for (int mt = 0; mt < 2; mt++) {
                    mma8(d[mt], Ah[mt][ks], b0h, b1h);
                    mma8(d[mt], Al[mt][ks], b0h, b1h);
                    mma8(d[mt], Ah[mt][ks], b0l, b1l);
                }
            }
            int i = nt >> 1, par = nt & 1;
            #pragma unroll
            for (int mt = 0; mt < 2; mt++) {
                int e0 = 32*wid + 16*mt + g, e1 = e0 + 8;
                msg[2*mt+0][par] = ffma2(pack2(s[S_XS + e0*XS_S + i]), packf(d[mt][0], d[mt][1]), msg[2*mt+0][par]);
                msg[2*mt+1][par] = ffma2(pack2(s[S_XS + e1*XS_S + i]), packf(d[mt][2], d[mt][3]), msg[2*mt+1][par]);
            }
        }

        // scatter max: 4 edges x 4 outputs, branch-free ordered-int RED.MAX
        #pragma unroll
        for (int j = 0; j < 4; j++) {
            int el = 32*wid + (j >> 1) * 16 + (j & 1) * 8 + g;
            int eg = tile * T + el;
            if (eg < E) {
                int* slot = &g_agg[(size_t)edge_index[E + eg] * OUT];
                float m0, m1, m2, m3;
                unpack2(msg[j][0], m0, m1);
                unpack2(msg[j][1], m2, m3);
                atomicMax(slot + 2*tig + 0, ford(m0));
                atomicMax(slot + 2*tig + 1, ford(m1));
                atomicMax(slot + 2*tig + 8, ford(m2));
                atomicMax(slot + 2*tig + 9, ford(m3));
            }
        }
        __syncwarp();
    }
}

__global__ __launch_bounds__(256)
void node_kernel(const float* __restrict__ node_feats,
                 const float* __restrict__ root_w,
                 const float* __restrict__ bias,
                 float* __restrict__ out, int N)
{
    __shared__ float rw[NODE_IN * OUT];
    __shared__ float bs[OUT];
    int tid = threadIdx.x;
    if (tid < NODE_IN * OUT) rw[tid] = root_w[tid];
    if (tid < OUT) bs[tid] = bias[tid];
    __syncthreads();

    int n = blockIdx.x * 256 + tid;
    if (n >= N) return;

    float xi[NODE_IN];
    {
        const float4* nf = (const float4*)(node_feats + (size_t)n * NODE_IN);
        float4 a = nf[0], b = nf[1], c = nf[2], d4 = nf[3];
        xi[0]=a.x;  xi[1]=a.y;  xi[2]=a.z;  xi[3]=a.w;
        xi[4]=b.x;  xi[5]=b.y;  xi[6]=b.z;  xi[7]=b.w;
        xi[8]=c.x;  xi[9]=c.y;  xi[10]=c.z; xi[11]=c.w;
        xi[12]=d4.x; xi[13]=d4.y; xi[14]=d4.z; xi[15]=d4.w;
    }

    float o[OUT];
    #pragma unroll
    for (int j = 0; j < OUT; j++) o[j] = bs[j];
    #pragma unroll
    for (int i = 0; i < NODE_IN; i++) {
        float xv = xi[i];
        #pragma unroll
        for (int j = 0; j < OUT; j++) o[j] = fmaf(xv, rw[i*OUT + j], o[j]);
    }

    #pragma unroll
    for (int j = 0; j < OUT; j++) {
        int a = g_agg[(size_t)n * OUT + j];
        float av;
        if (a == (int)0x80000000) av = 0.f;
        else av = __int_as_float(a >= 0 ? a : (a ^ 0x7fffffff));
        o[j] += av;
    }

    float4* ov = (float4*)(out + (size_t)n * OUT);
    ov[0] = make_float4(o[0],  o[1],  o[2],  o[3]);
    ov[1] = make_float4(o[4],  o[5],  o[6],  o[7]);
    ov[2] = make_float4(o[8],  o[9],  o[10], o[11]);
    ov[3] = make_float4(o[12], o[13], o[14], o[15]);
}

extern "C" void kernel_launch(void* const* d_in, const int* in_sizes, int n_in,
                              void* d_out, int out_size)
{
    const float* node_feats = (const float*)d_in[0];
    const int*   edge_index = (const int*)  d_in[1];
    const float* edge_feats = (const float*)d_in[2];
    const float* w0 = (const float*)d_in[3];
    const float* b0 = (const float*)d_in[4];
    const float* w1 = (const float*)d_in[5];
    const float* b1 = (const float*)d_in[6];
    const float* w2 = (const float*)d_in[7];
    const float* b2 = (const float*)d_in[8];
    const float* lw = (const float*)d_in[9];
    const float* lb = (const float*)d_in[10];
    const float* root_w = (const float*)d_in[11];
    const float* bias   = (const float*)d_in[12];

    int E = in_sizes[1] / 2;
    int N = in_sizes[0] / NODE_IN;

    cudaFuncSetAttribute(edge_kernel, cudaFuncAttributeMaxDynamicSharedMemorySize, SMEM_BYTES);

    init_agg_kernel<<<(N * OUT + 255) / 256, 256>>>(N * OUT);
    prep_lw_kernel<<<(WIDTH * NODE_IN * OUT + 255) / 256, 256>>>(lw);

    int ntiles = (E + T - 1) / T;
    int grid = ntiles < NBLK ? ntiles : NBLK;
    edge_kernel<<<grid, T, SMEM_BYTES>>>(
        node_feats, edge_index, edge_feats, w0, b0, w1, b1, w2, b2, lb, E);

    node_kernel<<<(N + 255) / 256, 256>>>(node_feats, root_w, bias, (float*)d_out, N);
}

// round 10
// speedup vs baseline: 1.6539x; 1.1164x over previous
#include <cuda_runtime.h>
#include <cuda_bf16.h>
#include <stdint.h>

#define EDGE_IN 19
#define WIDTH   64
#define NODE_IN 16
#define OUT     16
#define N_NODES_MAX 50000
#define T 256        // threads per block = edges per tile (32 per warp)
#define ACT_S 256    // act row stride (R6-proven; 4-way gather conflicts tolerated)
#define XS_S 20
#define NBLK 148

// ---- shared memory layout (float offsets, all 16B-aligned) ----
#define S_W0    0        // 1216 (raw fp32, FFMA2 layer0)
#define S_B0    1216     // 64
#define S_W1    1280     // 4096 (raw fp32, FFMA2 layer1)
#define S_B1    5376     // 64
#define S_W2F   5440     // 4096 (tf32-hi, B-frag order)
#define S_W2LO  9536     // 2048 (4096 bf16 lo residuals)
#define S_B2    11584    // 64
#define S_LWHI  11648    // 16384
#define S_LWLO  28032    // 8192
#define S_LB    36224    // 256
#define S_XS    36480    // 256*20 = 5120
#define S_ACT   41600    // 64*256 = 16384
#define SMEM_FLOATS 57984
#define SMEM_BYTES (SMEM_FLOATS*4)   // 231936 B

typedef unsigned long long u64;

__device__ __forceinline__ u64 ffma2(u64 a, u64 b, u64 c) {
    u64 d; asm("fma.rn.f32x2 %0, %1, %2, %3;" : "=l"(d) : "l"(a), "l"(b), "l"(c)); return d;
}
__device__ __forceinline__ u64 pack2(float x) {
    u64 r; asm("mov.b64 %0, {%1, %1};" : "=l"(r) : "f"(x)); return r;
}
__device__ __forceinline__ u64 packf(float lo, float hi) {
    u64 r; asm("mov.b64 %0, {%1, %2};" : "=l"(r) : "f"(lo), "f"(hi)); return r;
}
__device__ __forceinline__ void unpack2(u64 v, float& lo, float& hi) {
    asm("mov.b64 {%0, %1}, %2;" : "=f"(lo), "=f"(hi) : "l"(v));
}
__device__ __forceinline__ int ford(float f) {
    int b = __float_as_int(f); return b >= 0 ? b : (b ^ 0x7fffffff);
}
__device__ __forceinline__ unsigned tf32_of(float x) {
    unsigned r; asm("cvt.rna.tf32.f32 %0, %1;" : "=r"(r) : "f"(x)); return r;
}
__device__ __forceinline__ void mma8(float* d, const unsigned* a, unsigned b0, unsigned b1) {
    asm volatile("mma.sync.aligned.m16n8k8.row.col.f32.tf32.tf32.f32 "
        "{%0,%1,%2,%3}, {%4,%5,%6,%7}, {%8,%9}, {%0,%1,%2,%3};"
        : "+f"(d[0]), "+f"(d[1]), "+f"(d[2]), "+f"(d[3])
        : "r"(a[0]), "r"(a[1]), "r"(a[2]), "r"(a[3]), "r"(b0), "r"(b1));
}

__device__ int g_agg[N_NODES_MAX * OUT];
__device__ float         g_lwhi[WIDTH * NODE_IN * OUT];
__device__ __nv_bfloat16 g_lwlo[WIDTH * NODE_IN * OUT];
__device__ float         g_w2f[WIDTH * WIDTH];
__device__ __nv_bfloat16 g_w2lo[WIDTH * WIDTH];

__global__ void init_agg_kernel(int n) {
    int i = blockIdx.x * blockDim.x + threadIdx.x;
    if (i < n) g_agg[i] = (int)0x80000000;
}

// Split lin_w into tf32-hi + bf16-lo, B-fragment order (N=256) — R6-proven.
__global__ void prep_lw_kernel(const float* __restrict__ lw) {
    int idx = blockIdx.x * 256 + threadIdx.x;
    if (idx >= WIDTH * NODE_IN * OUT) return;
    int k = idx >> 8, nn = idx & 255;
    float w = lw[idx];
    float hif = __uint_as_float(tf32_of(w));
    int pos = (((k >> 3) * 32 + (nn >> 3)) * 32 + (nn & 7) * 4 + (k & 3)) * 2 + ((k & 7) >> 2);
    g_lwhi[pos] = hif;
    g_lwlo[pos] = __float2bfloat16(w - hif);
}

// Same split for w2 (N=64, NT=8).
__global__ void prep_w2_kernel(const float* __restrict__ w2) {
    int idx = blockIdx.x * 256 + threadIdx.x;
    if (idx >= WIDTH * WIDTH) return;
    int k = idx >> 6, nn = idx & 63;
    float w = w2[idx];
    float hif = __uint_as_float(tf32_of(w));
    int pos = (((k >> 3) * 8 + (nn >> 3)) * 32 + (nn & 7) * 4 + (k & 3)) * 2 + ((k & 7) >> 2);
    g_w2f[pos] = hif;
    g_w2lo[pos] = __float2bfloat16(w - hif);
}

__global__ __launch_bounds__(T, 1)
void edge_kernel(const float* __restrict__ node_feats,
                 const int*   __restrict__ edge_index,
                 const float* __restrict__ edge_feats,
                 const float* __restrict__ w0, const float* __restrict__ b0,
                 const float* __restrict__ w1, const float* __restrict__ b1,
                 const float* __restrict__ b2, const float* __restrict__ lb, int E)
{
    extern __shared__ float s[];
    const int tid = threadIdx.x;
    const int lane = tid & 31, wid = tid >> 5;
    const int g = lane >> 2, tig = lane & 3;

    { // cooperative constant load (once per persistent block)
        float4* d = (float4*)s; const float4* v;
        v = (const float4*)w0;      for (int i = tid; i < 304;  i += T) d[S_W0/4 + i]   = v[i];
        v = (const float4*)b0;      for (int i = tid; i < 16;   i += T) d[S_B0/4 + i]   = v[i];
        v = (const float4*)w1;      for (int i = tid; i < 1024; i += T) d[S_W1/4 + i]   = v[i];
        v = (const float4*)b1;      for (int i = tid; i < 16;   i += T) d[S_B1/4 + i]   = v[i];
        v = (const float4*)g_w2f;   for (int i = tid; i < 1024; i += T) d[S_W2F/4 + i]  = v[i];
        v = (const float4*)g_w2lo;  for (int i = tid; i < 512;  i += T) d[S_W2LO/4 + i] = v[i];
        v = (const float4*)b2;      for (int i = tid; i < 16;   i += T) d[S_B2/4 + i]   = v[i];
        v = (const float4*)g_lwhi;  for (int i = tid; i < 4096; i += T) d[S_LWHI/4 + i] = v[i];
        v = (const float4*)g_lwlo;  for (int i = tid; i < 2048; i += T) d[S_LWLO/4 + i] = v[i];
        v = (const float4*)lb;      for (int i = tid; i < 64;   i += T) d[S_LB/4 + i]   = v[i];
    }
    __syncthreads();

    float* act = s + S_ACT;
    const int ntiles = (E + T - 1) / T;

    for (int tile = blockIdx.x; tile < ntiles; tile += gridDim.x) {
        int e = tile * T + tid;
        int ee = (e < E) ? e : (E - 1);

        // stage this edge's features in own smem column
        #pragma unroll
        for (int k = 0; k < EDGE_IN; k++)
            act[k * ACT_S + tid] = edge_feats[(size_t)ee * EDGE_IN + k];

        u64 h2[WIDTH/2];
        // FFMA2 layer (R6-proven): K inputs -> 64 outputs, relu, back to act
        #define LAYER(K, SW, SB)                                                     \
        {                                                                            \
            const u64* __restrict__ bb = (const u64*)(s + (SB));                     \
            _Pragma("unroll")                                                        \
            for (int j = 0; j < WIDTH/2; j++) h2[j] = bb[j];                         \
            _Pragma("unroll 1")                                                      \
            for (int k = 0; k < (K); k++) {                                          \
                u64 x = pack2(act[k * ACT_S + tid]);                                 \
                const ulonglong2* __restrict__ wr =                                  \
                    (const ulonglong2*)(s + (SW) + k * WIDTH);                       \
                _Pragma("unroll")                                                    \
                for (int j = 0; j < WIDTH/4; j++) {                                  \
                    ulonglong2 w = wr[j];                                            \
                    h2[2*j+0] = ffma2(x, w.x, h2[2*j+0]);                            \
                    h2[2*j+1] = ffma2(x, w.y, h2[2*j+1]);                            \
                }                                                                    \
            }                                                                        \
            _Pragma("unroll")                                                        \
            for (int j = 0; j < WIDTH/2; j++) {                                      \
                float lo, hi; unpack2(h2[j], lo, hi);                                \
                act[(2*j+0) * ACT_S + tid] = fmaxf(lo, 0.f);                         \
                act[(2*j+1) * ACT_S + tid] = fmaxf(hi, 0.f);                         \
            }                                                                        \
        }

        LAYER(EDGE_IN, S_W0, S_B0)   // 19 -> 64 (FFMA2)
        LAYER(WIDTH,   S_W1, S_B1)   // 64 -> 64 (FFMA2)
        #undef LAYER
        __syncwarp();

        // ---- MMA layer2: h2 = relu(h1 @ w2 + b2), in place on act ----
        {
            unsigned Ah[2][8][4], Al[2][8][4];
            #pragma unroll
            for (int mt = 0; mt < 2; mt++)
                #pragma unroll
                for (int ks = 0; ks < 8; ks++)
                    #pragma unroll
                    for (int q = 0; q < 4; q++) {
                        int el = 32*wid + 16*mt + g + (q & 1) * 8;
                        int kk = 8*ks + tig + (q >> 1) * 4;
                        float v = act[kk * ACT_S + el];
                        unsigned hu = tf32_of(v);
                        Ah[mt][ks][q] = hu;
                        Al[mt][ks][q] = tf32_of(v - __uint_as_float(hu));
                    }
            __syncwarp();   // all gathers done before in-place writes

            #pragma unroll 1
            for (int nt = 0; nt < 8; nt++) {
                float bv0 = s[S_B2 + 8*nt + 2*tig];
                float bv1 = s[S_B2 + 8*nt + 2*tig + 1];
                float d[2][4] = {{bv0,bv1,bv0,bv1},{bv0,bv1,bv0,bv1}};
                #pragma unroll
                for (int ks = 0; ks < 8; ks++) {
                    int fidx = (ks * 8 + nt) * 32 + lane;
                    u64 bh = *(const u64*)(s + S_W2F + fidx * 2);
                    float bh0, bh1; unpack2(bh, bh0, bh1);
                    unsigned blo = *(const unsigned*)(s + S_W2LO + fidx);
                    unsigned b0h = __float_as_uint(bh0), b1h = __float_as_uint(bh1);
                    unsigned b0l = blo << 16, b1l = blo & 0xffff0000u;
                    #pragma unroll
                    for (int mt = 0; mt < 2; mt++) {
                        mma8(d[mt], Ah[mt][ks], b0h, b1h);
                        mma8(d[mt], Al[mt][ks], b0h, b1h);
                        mma8(d[mt], Ah[mt][ks], b0l, b1l);
                    }
                }
                int r0 = (8*nt + 2*tig) * ACT_S, r1 = r0 + ACT_S;
                #pragma unroll
                for (int mt = 0; mt < 2; mt++) {
                    int e0 = 32*wid + 16*mt + g, e1 = e0 + 8;
                    act[r0 + e0] = fmaxf(d[mt][0], 0.f);
                    act[r1 + e0] = fmaxf(d[mt][1], 0.f);
                    act[r0 + e1] = fmaxf(d[mt][2], 0.f);
                    act[r1 + e1] = fmaxf(d[mt][3], 0.f);
                }
            }
            __syncwarp();
        }
        // act rows 0..63 hold h2

        { // stage src node feats (row per edge)
            const float4* nf = (const float4*)(node_feats + (size_t)edge_index[ee] * NODE_IN);
            float4* xr = (float4*)(s + S_XS + tid * XS_S);
            xr[0] = nf[0]; xr[1] = nf[1]; xr[2] = nf[2]; xr[3] = nf[3];
        }
        __syncwarp();

        // ---- lw GEMM fused with x-contraction (R6-proven) ----
        unsigned Ah[2][8][4], Al[2][8][4];
        #pragma unroll
        for (int mt = 0; mt < 2; mt++)
            #pragma unroll
            for (int ks = 0; ks < 8; ks++)
                #pragma unroll
                for (int q = 0; q < 4; q++) {
                    int el = 32*wid + 16*mt + g + (q & 1) * 8;
                    int kk = 8*ks + tig + (q >> 1) * 4;
                    float v = act[kk * ACT_S + el];
                    unsigned hu = tf32_of(v);
                    Ah[mt][ks][q] = hu;
                    Al[mt][ks][q] = tf32_of(v - __uint_as_float(hu));
                }

        u64 msg[4][2];
        #pragma unroll
        for (int j = 0; j < 4; j++) { msg[j][0] = 0ull; msg[j][1] = 0ull; }
        #pragma unroll 1
        for (int i = 0; i < NODE_IN; i++) {
            u64 lb0 = *(const u64*)(s + S_LB + i*OUT + 2*tig);
            u64 lb1 = *(const u64*)(s + S_LB + i*OUT + 2*tig + 8);
            #pragma unroll
            for (int j = 0; j < 4; j++) {
                int el = 32*wid + (j >> 1) * 16 + (j & 1) * 8 + g;
                u64 xv = pack2(s[S_XS + el * XS_S + i]);
                msg[j][0] = ffma2(xv, lb0, msg[j][0]);
                msg[j][1] = ffma2(xv, lb1, msg[j][1]);
            }
        }

        #pragma unroll 1
        for (int nt = 0; nt < 32; nt++) {
            float d[2][4] = {{0,0,0,0},{0,0,0,0}};
            #pragma unroll
            for (int ks = 0; ks < 8; ks++) {
                int fidx = (ks * 32 + nt) * 32 + lane;
                u64 bh = *(const u64*)(s + S_LWHI + fidx * 2);
                float bh0, bh1; unpack2(bh, bh0, bh1);
                unsigned blo = *(const unsigned*)(s + S_LWLO + fidx);
                unsigned b0h = __float_as_uint(bh0), b1h = __float_as_uint(bh1);
                unsigned b0l = blo << 16, b1l = blo & 0xffff0000u;
                #pragma unroll
                for (int mt = 0; mt < 2; mt++) {
                    mma8(d[mt], Ah[mt][ks], b0h, b1h);
                    mma8(d[mt], Al[mt][ks], b0h, b1h);
                    mma8(d[mt], Ah[mt][ks], b0l, b1l);
                }
            }
            int i = nt >> 1, par = nt & 1;
            #pragma unroll
            for (int mt = 0; mt < 2; mt++) {
                int e0 = 32*wid + 16*mt + g, e1 = e0 + 8;
                msg[2*mt+0][par] = ffma2(pack2(s[S_XS + e0*XS_S + i]), packf(d[mt][0], d[mt][1]), msg[2*mt+0][par]);
                msg[2*mt+1][par] = ffma2(pack2(s[S_XS + e1*XS_S + i]), packf(d[mt][2], d[mt][3]), msg[2*mt+1][par]);
            }
        }

        // scatter max: branch-free ordered-int RED.MAX
        #pragma unroll
        for (int j = 0; j < 4; j++) {
            int el = 32*wid + (j >> 1) * 16 + (j & 1) * 8 + g;
            int eg = tile * T + el;
            if (eg < E) {
                int* slot = &g_agg[(size_t)edge_index[E + eg] * OUT];
                float m0, m1, m2, m3;
                unpack2(msg[j][0], m0, m1);
                unpack2(msg[j][1], m2, m3);
                atomicMax(slot + 2*tig + 0, ford(m0));
                atomicMax(slot + 2*tig + 1, ford(m1));
                atomicMax(slot + 2*tig + 8, ford(m2));
                atomicMax(slot + 2*tig + 9, ford(m3));
            }
        }
        __syncwarp();
    }
}

__global__ __launch_bounds__(256)
void node_kernel(const float* __restrict__ node_feats,
                 const float* __restrict__ root_w,
                 const float* __restrict__ bias,
                 float* __restrict__ out, int N)
{
    __shared__ float rw[NODE_IN * OUT];
    __shared__ float bs[OUT];
    int tid = threadIdx.x;
    if (tid < NODE_IN * OUT) rw[tid] = root_w[tid];
    if (tid < OUT) bs[tid] = bias[tid];
    __syncthreads();

    int n = blockIdx.x * 256 + tid;
    if (n >= N) return;

    float xi[NODE_IN];
    {
        const float4* nf = (const float4*)(node_feats + (size_t)n * NODE_IN);
        float4 a = nf[0], b = nf[1], c = nf[2], d4 = nf[3];
        xi[0]=a.x;  xi[1]=a.y;  xi[2]=a.z;  xi[3]=a.w;
        xi[4]=b.x;  xi[5]=b.y;  xi[6]=b.z;  xi[7]=b.w;
        xi[8]=c.x;  xi[9]=c.y;  xi[10]=c.z; xi[11]=c.w;
        xi[12]=d4.x; xi[13]=d4.y; xi[14]=d4.z; xi[15]=d4.w;
    }

    float o[OUT];
    #pragma unroll
    for (int j = 0; j < OUT; j++) o[j] = bs[j];
    #pragma unroll
    for (int i = 0; i < NODE_IN; i++) {
        float xv = xi[i];
        #pragma unroll
        for (int j = 0; j < OUT; j++) o[j] = fmaf(xv, rw[i*OUT + j], o[j]);
    }

    #pragma unroll
    for (int j = 0; j < OUT; j++) {
        int a = g_agg[(size_t)n * OUT + j];
        float av;
        if (a == (int)0x80000000) av = 0.f;
        else av = __int_as_float(a >= 0 ? a : (a ^ 0x7fffffff));
        o[j] += av;
    }

    float4* ov = (float4*)(out + (size_t)n * OUT);
    ov[0] = make_float4(o[0],  o[1],  o[2],  o[3]);
    ov[1] = make_float4(o[4],  o[5],  o[6],  o[7]);
    ov[2] = make_float4(o[8],  o[9],  o[10], o[11]);
    ov[3] = make_float4(o[12], o[13], o[14], o[15]);
}

extern "C" void kernel_launch(void* const* d_in, const int* in_sizes, int n_in,
                              void* d_out, int out_size)
{
    const float* node_feats = (const float*)d_in[0];
    const int*   edge_index = (const int*)  d_in[1];
    const float* edge_feats = (const float*)d_in[2];
    const float* w0 = (const float*)d_in[3];
    const float* b0 = (const float*)d_in[4];
    const float* w1 = (const float*)d_in[5];
    const float* b1 = (const float*)d_in[6];
    const float* w2 = (const float*)d_in[7];
    const float* b2 = (const float*)d_in[8];
    const float* lw = (const float*)d_in[9];
    const float* lb = (const float*)d_in[10];
    const float* root_w = (const float*)d_in[11];
    const float* bias   = (const float*)d_in[12];

    int E = in_sizes[1] / 2;
    int N = in_sizes[0] / NODE_IN;

    cudaFuncSetAttribute(edge_kernel, cudaFuncAttributeMaxDynamicSharedMemorySize, SMEM_BYTES);

    init_agg_kernel<<<(N * OUT + 255) / 256, 256>>>(N * OUT);
    prep_lw_kernel<<<(WIDTH * NODE_IN * OUT + 255) / 256, 256>>>(lw);
    prep_w2_kernel<<<(WIDTH * WIDTH + 255) / 256, 256>>>(w2);

    int ntiles = (E + T - 1) / T;
    int grid = ntiles < NBLK ? ntiles : NBLK;
    edge_kernel<<<grid, T, SMEM_BYTES>>>(
        node_feats, edge_index, edge_feats, w0, b0, w1, b1, b2, lb, E);

    node_kernel<<<(N + 255) / 256, 256>>>(node_feats, root_w, bias, (float*)d_out, N);
}

// round 13
// speedup vs baseline: 1.6744x; 1.0124x over previous
#include <cuda_runtime.h>
#include <cuda_bf16.h>
#include <stdint.h>

#define EDGE_IN 19
#define WIDTH   64
#define NODE_IN 16
#define OUT     16
#define N_NODES_MAX 50000
#define T 256        // threads per block = edges per tile (32 per warp)
#define ACT_S 264    // ==8 mod 32 -> conflict-free A-frag gathers
#define XS_S 16      // 64B-aligned rows (float4-safe); minor read conflicts OK
#define NBLK 148

// ---- shared memory layout (float offsets, all 16B-aligned) ----
#define S_W0    0        // 1216 (raw fp32, FFMA2 layer0)
#define S_B0    1216     // 64
#define S_W1    1280     // 4096 (raw fp32, FFMA2 layer1)
#define S_B1    5376     // 64
#define S_W2F   5440     // 4096 (tf32-hi, B-frag order)
#define S_W2LO  9536     // 2048 (4096 bf16 lo residuals)
#define S_B2    11584    // 64
#define S_LWHI  11648    // 16384
#define S_LWLO  28032    // 8192
#define S_LB    36224    // 256
#define S_XS    36480    // 256*16 = 4096
#define S_ACT   40576    // 64*264 = 16896
#define SMEM_FLOATS 57472
#define SMEM_BYTES (SMEM_FLOATS*4)   // 229888 B

typedef unsigned long long u64;

__device__ __forceinline__ u64 ffma2(u64 a, u64 b, u64 c) {
    u64 d; asm("fma.rn.f32x2 %0, %1, %2, %3;" : "=l"(d) : "l"(a), "l"(b), "l"(c)); return d;
}
__device__ __forceinline__ u64 pack2(float x) {
    u64 r; asm("mov.b64 %0, {%1, %1};" : "=l"(r) : "f"(x)); return r;
}
__device__ __forceinline__ u64 packf(float lo, float hi) {
    u64 r; asm("mov.b64 %0, {%1, %2};" : "=l"(r) : "f"(lo), "f"(hi)); return r;
}
__device__ __forceinline__ void unpack2(u64 v, float& lo, float& hi) {
    asm("mov.b64 {%0, %1}, %2;" : "=f"(lo), "=f"(hi) : "l"(v));
}
__device__ __forceinline__ int ford(float f) {
    int b = __float_as_int(f); return b >= 0 ? b : (b ^ 0x7fffffff);
}
__device__ __forceinline__ unsigned tf32_of(float x) {
    unsigned r; asm("cvt.rna.tf32.f32 %0, %1;" : "=r"(r) : "f"(x)); return r;
}
__device__ __forceinline__ void mma8(float* d, const unsigned* a, unsigned b0, unsigned b1) {
    asm volatile("mma.sync.aligned.m16n8k8.row.col.f32.tf32.tf32.f32 "
        "{%0,%1,%2,%3}, {%4,%5,%6,%7}, {%8,%9}, {%0,%1,%2,%3};"
        : "+f"(d[0]), "+f"(d[1]), "+f"(d[2]), "+f"(d[3])
        : "r"(a[0]), "r"(a[1]), "r"(a[2]), "r"(a[3]), "r"(b0), "r"(b1));
}

__device__ int g_agg[N_NODES_MAX * OUT];
__device__ float         g_lwhi[WIDTH * NODE_IN * OUT];
__device__ __nv_bfloat16 g_lwlo[WIDTH * NODE_IN * OUT];
__device__ float         g_w2f[WIDTH * WIDTH];
__device__ __nv_bfloat16 g_w2lo[WIDTH * WIDTH];

__global__ void init_agg_kernel(int n) {
    int i = blockIdx.x * blockDim.x + threadIdx.x;
    if (i < n) g_agg[i] = (int)0x80000000;
}

// Split lin_w into tf32-hi + bf16-lo, B-fragment order (N=256) — proven.
__global__ void prep_lw_kernel(const float* __restrict__ lw) {
    int idx = blockIdx.x * 256 + threadIdx.x;
    if (idx >= WIDTH * NODE_IN * OUT) return;
    int k = idx >> 8, nn = idx & 255;
    float w = lw[idx];
    float hif = __uint_as_float(tf32_of(w));
    int pos = (((k >> 3) * 32 + (nn >> 3)) * 32 + (nn & 7) * 4 + (k & 3)) * 2 + ((k & 7) >> 2);
    g_lwhi[pos] = hif;
    g_lwlo[pos] = __float2bfloat16(w - hif);
}

// Same split for w2 (N=64, NT=8) — proven.
__global__ void prep_w2_kernel(const float* __restrict__ w2) {
    int idx = blockIdx.x * 256 + threadIdx.x;
    if (idx >= WIDTH * WIDTH) return;
    int k = idx >> 6, nn = idx & 63;
    float w = w2[idx];
    float hif = __uint_as_float(tf32_of(w));
    int pos = (((k >> 3) * 8 + (nn >> 3)) * 32 + (nn & 7) * 4 + (k & 3)) * 2 + ((k & 7) >> 2);
    g_w2f[pos] = hif;
    g_w2lo[pos] = __float2bfloat16(w - hif);
}

__global__ __launch_bounds__(T, 1)
void edge_kernel(const float* __restrict__ node_feats,
                 const int*   __restrict__ edge_index,
                 const float* __restrict__ edge_feats,
                 const float* __restrict__ w0, const float* __restrict__ b0,
                 const float* __restrict__ w1, const float* __restrict__ b1,
                 const float* __restrict__ b2, const float* __restrict__ lb, int E)
{
    extern __shared__ float s[];
    const int tid = threadIdx.x;
    const int lane = tid & 31, wid = tid >> 5;
    const int g = lane >> 2, tig = lane & 3;

    { // cooperative constant load (once per persistent block)
        float4* d = (float4*)s; const float4* v;
        v = (const float4*)w0;      for (int i = tid; i < 304;  i += T) d[S_W0/4 + i]   = v[i];
        v = (const float4*)b0;      for (int i = tid; i < 16;   i += T) d[S_B0/4 + i]   = v[i];
        v = (const float4*)w1;      for (int i = tid; i < 1024; i += T) d[S_W1/4 + i]   = v[i];
        v = (const float4*)b1;      for (int i = tid; i < 16;   i += T) d[S_B1/4 + i]   = v[i];
        v = (const float4*)g_w2f;   for (int i = tid; i < 1024; i += T) d[S_W2F/4 + i]  = v[i];
        v = (const float4*)g_w2lo;  for (int i = tid; i < 512;  i += T) d[S_W2LO/4 + i] = v[i];
        v = (const float4*)b2;      for (int i = tid; i < 16;   i += T) d[S_B2/4 + i]   = v[i];
        v = (const float4*)g_lwhi;  for (int i = tid; i < 4096; i += T) d[S_LWHI/4 + i] = v[i];
        v = (const float4*)g_lwlo;  for (int i = tid; i < 2048; i += T) d[S_LWLO/4 + i] = v[i];
        v = (const float4*)lb;      for (int i = tid; i < 64;   i += T) d[S_LB/4 + i]   = v[i];
    }
    __syncthreads();

    float* act = s + S_ACT;
    const int ntiles = (E + T - 1) / T;

    for (int tile = blockIdx.x; tile < ntiles; tile += gridDim.x) {
        int e = tile * T + tid;
        int ee = (e < E) ? e : (E - 1);

        // stage this edge's features in own smem column
        #pragma unroll
        for (int k = 0; k < EDGE_IN; k++)
            act[k * ACT_S + tid] = edge_feats[(size_t)ee * EDGE_IN + k];

        u64 h2[WIDTH/2];
        // FFMA2 layer (proven): K inputs -> 64 outputs, relu, back to act
        #define LAYER(K, SW, SB)                                                     \
        {                                                                            \
            const u64* __restrict__ bb = (const u64*)(s + (SB));                     \
            _Pragma("unroll")                                                        \
            for (int j = 0; j < WIDTH/2; j++) h2[j] = bb[j];                         \
            _Pragma("unroll 1")                                                      \
            for (int k = 0; k < (K); k++) {                                          \
                u64 x = pack2(act[k * ACT_S + tid]);                                 \
                const ulonglong2* __restrict__ wr =                                  \
                    (const ulonglong2*)(s + (SW) + k * WIDTH);                       \
                _Pragma("unroll")                                                    \
                for (int j = 0; j < WIDTH/4; j++) {                                  \
                    ulonglong2 w = wr[j];                                            \
                    h2[2*j+0] = ffma2(x, w.x, h2[2*j+0]);                            \
                    h2[2*j+1] = ffma2(x, w.y, h2[2*j+1]);                            \
                }                                                                    \
            }                                                                        \
            _Pragma("unroll")                                                        \
            for (int j = 0; j < WIDTH/2; j++) {                                      \
                float lo, hi; unpack2(h2[j], lo, hi);                                \
                act[(2*j+0) * ACT_S + tid] = fmaxf(lo, 0.f);                         \
                act[(2*j+1) * ACT_S + tid] = fmaxf(hi, 0.f);                         \
            }                                                                        \
        }

        LAYER(EDGE_IN, S_W0, S_B0)   // 19 -> 64 (FFMA2)
        LAYER(WIDTH,   S_W1, S_B1)   // 64 -> 64 (FFMA2)
        #undef LAYER
        __syncwarp();

        // ---- MMA layer2: h2 = relu(h1 @ w2 + b2), in place on act ----
        {
            unsigned Ah[2][8][4], Al[2][8][4];
            #pragma unroll
            for (int mt = 0; mt < 2; mt++)
                #pragma unroll
                for (int ks = 0; ks < 8; ks++)
                    #pragma unroll
                    for (int q = 0; q < 4; q++) {
                        int el = 32*wid + 16*mt + g + (q & 1) * 8;
                        int kk = 8*ks + tig + (q >> 1) * 4;
                        float v = act[kk * ACT_S + el];
                        unsigned hu = tf32_of(v);
                        Ah[mt][ks][q] = hu;
                        Al[mt][ks][q] = tf32_of(v - __uint_as_float(hu));
                    }
            __syncwarp();   // all gathers done before in-place writes

            #pragma unroll 1
            for (int nt = 0; nt < 8; nt++) {
                float bv0 = s[S_B2 + 8*nt + 2*tig];
                float bv1 = s[S_B2 + 8*nt + 2*tig + 1];
                float d[2][4] = {{bv0,bv1,bv0,bv1},{bv0,bv1,bv0,bv1}};
                #pragma unroll
                for (int ks = 0; ks < 8; ks++) {
                    int fidx = (ks * 8 + nt) * 32 + lane;
                    u64 bh = *(const u64*)(s + S_W2F + fidx * 2);
                    float bh0, bh1; unpack2(bh, bh0, bh1);
                    unsigned blo = *(const unsigned*)(s + S_W2LO + fidx);
                    unsigned b0h = __float_as_uint(bh0), b1h = __float_as_uint(bh1);
                    unsigned b0l = blo << 16, b1l = blo & 0xffff0000u;
                    #pragma unroll
                    for (int mt = 0; mt < 2; mt++) {
                        mma8(d[mt], Ah[mt][ks], b0h, b1h);
                        mma8(d[mt], Al[mt][ks], b0h, b1h);
                        mma8(d[mt], Ah[mt][ks], b0l, b1l);
                    }
                }
                int r0 = (8*nt + 2*tig) * ACT_S, r1 = r0 + ACT_S;
                #pragma unroll
                for (int mt = 0; mt < 2; mt++) {
                    int e0 = 32*wid + 16*mt + g, e1 = e0 + 8;
                    act[r0 + e0] = fmaxf(d[mt][0], 0.f);
                    act[r1 + e0] = fmaxf(d[mt][1], 0.f);
                    act[r0 + e1] = fmaxf(d[mt][2], 0.f);
                    act[r1 + e1] = fmaxf(d[mt][3], 0.f);
                }
            }
            __syncwarp();
        }
        // act rows 0..63 hold h2

        { // stage src node feats (row per edge)
            const float4* nf = (const float4*)(node_feats + (size_t)edge_index[ee] * NODE_IN);
            float4* xr = (float4*)(s + S_XS + tid * XS_S);
            xr[0] = nf[0]; xr[1] = nf[1]; xr[2] = nf[2]; xr[3] = nf[3];
        }
        __syncwarp();

        // ---- lw GEMM fused with x-contraction (proven) ----
        unsigned Ah[2][8][4], Al[2][8][4];
        #pragma unroll
        for (int mt = 0; mt < 2; mt++)
            #pragma unroll
            for (int ks = 0; ks < 8; ks++)
                #pragma unroll
                for (int q = 0; q < 4; q++) {
                    int el = 32*wid + 16*mt + g + (q & 1) * 8;
                    int kk = 8*ks + tig + (q >> 1) * 4;
                    float v = act[kk * ACT_S + el];
                    unsigned hu = tf32_of(v);
                    Ah[mt][ks][q] = hu;
                    Al[mt][ks][q] = tf32_of(v - __uint_as_float(hu));
                }

        u64 msg[4][2];
        #pragma unroll
        for (int j = 0; j < 4; j++) { msg[j][0] = 0ull; msg[j][1] = 0ull; }
        #pragma unroll 1
        for (int i = 0; i < NODE_IN; i++) {
            u64 lb0 = *(const u64*)(s + S_LB + i*OUT + 2*tig);
            u64 lb1 = *(const u64*)(s + S_LB + i*OUT + 2*tig + 8);
            #pragma unroll
            for (int j = 0; j < 4; j++) {
                int el = 32*wid + (j >> 1) * 16 + (j & 1) * 8 + g;
                u64 xv = pack2(s[S_XS + el * XS_S + i]);
                msg[j][0] = ffma2(xv, lb0, msg[j][0]);
                msg[j][1] = ffma2(xv, lb1, msg[j][1]);
            }
        }

        #pragma unroll 1
        for (int nt = 0; nt < 32; nt++) {
            float d[2][4] = {{0,0,0,0},{0,0,0,0}};
            #pragma unroll
            for (int ks = 0; ks < 8; ks++) {
                int fidx = (ks * 32 + nt) * 32 + lane;
                u64 bh = *(const u64*)(s + S_LWHI + fidx * 2);
                float bh0, bh1; unpack2(bh, bh0, bh1);
                unsigned blo = *(const unsigned*)(s + S_LWLO + fidx);
                unsigned b0h = __float_as_uint(bh0), b1h = __float_as_uint(bh1);
                unsigned b0l = blo << 16, b1l = blo & 0xffff0000u;
                #pragma unroll
                for (int mt = 0; mt < 2; mt++) {
                    mma8(d[mt], Ah[mt][ks], b0h, b1h);
                    mma8(d[mt], Al[mt][ks], b0h, b1h);
                    mma8(d[mt], Ah[mt][ks], b0l, b1l);
                }
            }
            int i = nt >> 1, par = nt & 1;
            #pragma unroll
            for (int mt = 0; mt < 2; mt++) {
                int e0 = 32*wid + 16*mt + g, e1 = e0 + 8;
                msg[2*mt+0][par] = ffma2(pack2(s[S_XS + e0*XS_S + i]), packf(d[mt][0], d[mt][1]), msg[2*mt+0][par]);
                msg[2*mt+1][par] = ffma2(pack2(s[S_XS + e1*XS_S + i]), packf(d[mt][2], d[mt][3]), msg[2*mt+1][par]);
            }
        }

        // scatter max: branch-free ordered-int RED.MAX
        #pragma unroll
        for (int j = 0; j < 4; j++) {
            int el = 32*wid + (j >> 1) * 16 + (j & 1) * 8 + g;
            int eg = tile * T + el;
            if (eg < E) {
                int* slot = &g_agg[(size_t)edge_index[E + eg] * OUT];
                float m0, m1, m2, m3;
                unpack2(msg[j][0], m0, m1);
                unpack2(msg[j][1], m2, m3);
                atomicMax(slot + 2*tig + 0, ford(m0));
                atomicMax(slot + 2*tig + 1, ford(m1));
                atomicMax(slot + 2*tig + 8, ford(m2));
                atomicMax(slot + 2*tig + 9, ford(m3));
            }
        }
        __syncwarp();
    }
}

__global__ __launch_bounds__(256)
void node_kernel(const float* __restrict__ node_feats,
                 const float* __restrict__ root_w,
                 const float* __restrict__ bias,
                 float* __restrict__ out, int N)
{
    __shared__ float rw[NODE_IN * OUT];
    __shared__ float bs[OUT];
    int tid = threadIdx.x;
    if (tid < NODE_IN * OUT) rw[tid] = root_w[tid];
    if (tid < OUT) bs[tid] = bias[tid];
    __syncthreads();

    int n = blockIdx.x * 256 + tid;
    if (n >= N) return;

    float xi[NODE_IN];
    {
        const float4* nf = (const float4*)(node_feats + (size_t)n * NODE_IN);
        float4 a = nf[0], b = nf[1], c = nf[2], d4 = nf[3];
        xi[0]=a.x;  xi[1]=a.y;  xi[2]=a.z;  xi[3]=a.w;
        xi[4]=b.x;  xi[5]=b.y;  xi[6]=b.z;  xi[7]=b.w;
        xi[8]=c.x;  xi[9]=c.y;  xi[10]=c.z; xi[11]=c.w;
        xi[12]=d4.x; xi[13]=d4.y; xi[14]=d4.z; xi[15]=d4.w;
    }

    float o[OUT];
    #pragma unroll
    for (int j = 0; j < OUT; j++) o[j] = bs[j];
    #pragma unroll
    for (int i = 0; i < NODE_IN; i++) {
        float xv = xi[i];
        #pragma unroll
        for (int j = 0; j < OUT; j++) o[j] = fmaf(xv, rw[i*OUT + j], o[j]);
    }

    #pragma unroll
    for (int j = 0; j < OUT; j++) {
        int a = g_agg[(size_t)n * OUT + j];
        float av;
        if (a == (int)0x80000000) av = 0.f;
        else av = __int_as_float(a >= 0 ? a : (a ^ 0x7fffffff));
        o[j] += av;
    }

    float4* ov = (float4*)(out + (size_t)n * OUT);
    ov[0] = make_float4(o[0],  o[1],  o[2],  o[3]);
    ov[1] = make_float4(o[4],  o[5],  o[6],  o[7]);
    ov[2] = make_float4(o[8],  o[9],  o[10], o[11]);
    ov[3] = make_float4(o[12], o[13], o[14], o[15]);
}

extern "C" void kernel_launch(void* const* d_in, const int* in_sizes, int n_in,
                              void* d_out, int out_size)
{
    const float* node_feats = (const float*)d_in[0];
    const int*   edge_index = (const int*)  d_in[1];
    const float* edge_feats = (const float*)d_in[2];
    const float* w0 = (const float*)d_in[3];
    const float* b0 = (const float*)d_in[4];
    const float* w1 = (const float*)d_in[5];
    const float* b1 = (const float*)d_in[6];
    const float* w2 = (const float*)d_in[7];
    const float* b2 = (const float*)d_in[8];
    const float* lw = (const float*)d_in[9];
    const float* lb = (const float*)d_in[10];
    const float* root_w = (const float*)d_in[11];
    const float* bias   = (const float*)d_in[12];

    int E = in_sizes[1] / 2;
    int N = in_sizes[0] / NODE_IN;

    cudaFuncSetAttribute(edge_kernel, cudaFuncAttributeMaxDynamicSharedMemorySize, SMEM_BYTES);

    init_agg_kernel<<<(N * OUT + 255) / 256, 256>>>(N * OUT);
    prep_lw_kernel<<<(WIDTH * NODE_IN * OUT + 255) / 256, 256>>>(lw);
    prep_w2_kernel<<<(WIDTH * WIDTH + 255) / 256, 256>>>(w2);

    int ntiles = (E + T - 1) / T;
    int grid = ntiles < NBLK ? ntiles : NBLK;
    edge_kernel<<<grid, T, SMEM_BYTES>>>(
        node_feats, edge_index, edge_feats, w0, b0, w1, b1, b2, lb, E);

    node_kernel<<<(N + 255) / 256, 256>>>(node_feats, root_w, bias, (float*)d_out, N);
}

// round 16
// speedup vs baseline: 1.7841x; 1.0655x over previous
#include <cuda_runtime.h>
#include <cuda_bf16.h>
#include <stdint.h>

#define EDGE_IN 19
#define WIDTH   64
#define NODE_IN 16
#define OUT     16
#define N_NODES_MAX 50000
#define T 224        // threads per block = edges per tile (7 warps)
#define ACT_S 232    // ==8 mod 32 -> conflict-free A-frag gathers
#define XS_S 16
#define NBLK 148

// ---- shared memory layout (float offsets, all 16B-aligned) ----
#define S_W0    0        // 1216 (raw fp32, FFMA2 layer0)
#define S_B0    1216     // 64
#define S_B1    1280     // 64
#define S_B2    1344     // 64
#define S_LB    1408     // 256
#define S_W1F   1664     // 4096 (tf32-hi, B-frag order)
#define S_W1LO  5760     // 2048 (4096 bf16)
#define S_W2F   7808     // 4096
#define S_W2LO  11904    // 2048
#define S_LWHI  13952    // 16384
#define S_LWLO  30336    // 8192
#define S_XS    38528    // 224*16 = 3584
#define S_ACT   42112    // 64*232 = 14848
#define SMEM_FLOATS 56960
#define SMEM_BYTES (SMEM_FLOATS*4)   // 227840 B

typedef unsigned long long u64;

__device__ __forceinline__ u64 ffma2(u64 a, u64 b, u64 c) {
    u64 d; asm("fma.rn.f32x2 %0, %1, %2, %3;" : "=l"(d) : "l"(a), "l"(b), "l"(c)); return d;
}
__device__ __forceinline__ u64 pack2(float x) {
    u64 r; asm("mov.b64 %0, {%1, %1};" : "=l"(r) : "f"(x)); return r;
}
__device__ __forceinline__ u64 packf(float lo, float hi) {
    u64 r; asm("mov.b64 %0, {%1, %2};" : "=l"(r) : "f"(lo), "f"(hi)); return r;
}
__device__ __forceinline__ void unpack2(u64 v, float& lo, float& hi) {
    asm("mov.b64 {%0, %1}, %2;" : "=f"(lo), "=f"(hi) : "l"(v));
}
__device__ __forceinline__ int ford(float f) {
    int b = __float_as_int(f); return b >= 0 ? b : (b ^ 0x7fffffff);
}
__device__ __forceinline__ unsigned tf32_of(float x) {
    unsigned r; asm("cvt.rna.tf32.f32 %0, %1;" : "=r"(r) : "f"(x)); return r;
}
__device__ __forceinline__ void mma8(float* d, const unsigned* a, unsigned b0, unsigned b1) {
    asm volatile("mma.sync.aligned.m16n8k8.row.col.f32.tf32.tf32.f32 "
        "{%0,%1,%2,%3}, {%4,%5,%6,%7}, {%8,%9}, {%0,%1,%2,%3};"
        : "+f"(d[0]), "+f"(d[1]), "+f"(d[2]), "+f"(d[3])
        : "r"(a[0]), "r"(a[1]), "r"(a[2]), "r"(a[3]), "r"(b0), "r"(b1));
}

__device__ int g_agg[N_NODES_MAX * OUT];
__device__ float         g_lwhi[WIDTH * NODE_IN * OUT];
__device__ __nv_bfloat16 g_lwlo[WIDTH * NODE_IN * OUT];
__device__ float         g_w1f[WIDTH * WIDTH];
__device__ __nv_bfloat16 g_w1lo[WIDTH * WIDTH];
__device__ float         g_w2f[WIDTH * WIDTH];
__device__ __nv_bfloat16 g_w2lo[WIDTH * WIDTH];

__global__ void init_agg_kernel(int n) {
    int i = blockIdx.x * blockDim.x + threadIdx.x;
    if (i < n) g_agg[i] = (int)0x80000000;
}

// Split lin_w into tf32-hi + bf16-lo, B-fragment order (N=256).
// Writes __device__ globals BY NAME (host-passed global pointers are invalid!).
__global__ void prep_lw_kernel(const float* __restrict__ lw) {
    int idx = blockIdx.x * 256 + threadIdx.x;
    if (idx >= WIDTH * NODE_IN * OUT) return;
    int k = idx >> 8, nn = idx & 255;
    float w = lw[idx];
    float hif = __uint_as_float(tf32_of(w));
    int pos = (((k >> 3) * 32 + (nn >> 3)) * 32 + (nn & 7) * 4 + (k & 3)) * 2 + ((k & 7) >> 2);
    g_lwhi[pos] = hif;
    g_lwlo[pos] = __float2bfloat16(w - hif);
}

// Same split for w1 (N=64, NT=8) — writes globals by name.
__global__ void prep_w1_kernel(const float* __restrict__ w) {
    int idx = blockIdx.x * 256 + threadIdx.x;
    if (idx >= WIDTH * WIDTH) return;
    int k = idx >> 6, nn = idx & 63;
    float v = w[idx];
    float hif = __uint_as_float(tf32_of(v));
    int pos = (((k >> 3) * 8 + (nn >> 3)) * 32 + (nn & 7) * 4 + (k & 3)) * 2 + ((k & 7) >> 2);
    g_w1f[pos] = hif;
    g_w1lo[pos] = __float2bfloat16(v - hif);
}

// Same split for w2 — writes globals by name.
__global__ void prep_w2_kernel(const float* __restrict__ w) {
    int idx = blockIdx.x * 256 + threadIdx.x;
    if (idx >= WIDTH * WIDTH) return;
    int k = idx >> 6, nn = idx & 63;
    float v = w[idx];
    float hif = __uint_as_float(tf32_of(v));
    int pos = (((k >> 3) * 8 + (nn >> 3)) * 32 + (nn & 7) * 4 + (k & 3)) * 2 + ((k & 7) >> 2);
    g_w2f[pos] = hif;
    g_w2lo[pos] = __float2bfloat16(v - hif);
}

__global__ __launch_bounds__(T, 1)
void edge_kernel(const float* __restrict__ node_feats,
                 const int*   __restrict__ edge_index,
                 const float* __restrict__ edge_feats,
                 const float* __restrict__ w0, const float* __restrict__ b0,
                 const float* __restrict__ b1, const float* __restrict__ b2,
                 const float* __restrict__ lb, int E)
{
    extern __shared__ float s[];
    const int tid = threadIdx.x;
    const int lane = tid & 31, wid = tid >> 5;
    const int g = lane >> 2, tig = lane & 3;

    { // cooperative constant load (once per persistent block)
        float4* d = (float4*)s; const float4* v;
        v = (const float4*)w0;      for (int i = tid; i < 304;  i += T) d[S_W0/4 + i]   = v[i];
        v = (const float4*)b0;      for (int i = tid; i < 16;   i += T) d[S_B0/4 + i]   = v[i];
        v = (const float4*)b1;      for (int i = tid; i < 16;   i += T) d[S_B1/4 + i]   = v[i];
        v = (const float4*)b2;      for (int i = tid; i < 16;   i += T) d[S_B2/4 + i]   = v[i];
        v = (const float4*)lb;      for (int i = tid; i < 64;   i += T) d[S_LB/4 + i]   = v[i];
        v = (const float4*)g_w1f;   for (int i = tid; i < 1024; i += T) d[S_W1F/4 + i]  = v[i];
        v = (const float4*)g_w1lo;  for (int i = tid; i < 512;  i += T) d[S_W1LO/4 + i] = v[i];
        v = (const float4*)g_w2f;   for (int i = tid; i < 1024; i += T) d[S_W2F/4 + i]  = v[i];
        v = (const float4*)g_w2lo;  for (int i = tid; i < 512;  i += T) d[S_W2LO/4 + i] = v[i];
        v = (const float4*)g_lwhi;  for (int i = tid; i < 4096; i += T) d[S_LWHI/4 + i] = v[i];
        v = (const float4*)g_lwlo;  for (int i = tid; i < 2048; i += T) d[S_LWLO/4 + i] = v[i];
    }
    __syncthreads();

    float* act = s + S_ACT;
    const int ntiles = (E + T - 1) / T;

    for (int tile = blockIdx.x; tile < ntiles; tile += gridDim.x) {
        int e = tile * T + tid;
        int ee = (e < E) ? e : (E - 1);

        // stage this edge's features in own smem column
        #pragma unroll
        for (int k = 0; k < EDGE_IN; k++)
            act[k * ACT_S + tid] = edge_feats[(size_t)ee * EDGE_IN + k];

        // ---- layer0 (19->64) FFMA2 (proven) ----
        {
            u64 h2[WIDTH/2];
            const u64* __restrict__ bb = (const u64*)(s + S_B0);
            #pragma unroll
            for (int j = 0; j < WIDTH/2; j++) h2[j] = bb[j];
            #pragma unroll 1
            for (int k = 0; k < EDGE_IN; k++) {
                u64 x = pack2(act[k * ACT_S + tid]);
                const ulonglong2* __restrict__ wr = (const ulonglong2*)(s + S_W0 + k * WIDTH);
                #pragma unroll
                for (int j = 0; j < WIDTH/4; j++) {
                    ulonglong2 w = wr[j];
                    h2[2*j+0] = ffma2(x, w.x, h2[2*j+0]);
                    h2[2*j+1] = ffma2(x, w.y, h2[2*j+1]);
                }
            }
            #pragma unroll
            for (int j = 0; j < WIDTH/2; j++) {
                float lo, hi; unpack2(h2[j], lo, hi);
                act[(2*j+0) * ACT_S + tid] = fmaxf(lo, 0.f);
                act[(2*j+1) * ACT_S + tid] = fmaxf(hi, 0.f);
            }
        }
        __syncwarp();

        // ---- MLP MMA stages 1 & 2 in ONE code instantiation (stage loop) ----
        #pragma unroll 1
        for (int stage = 0; stage < 2; stage++) {
            const int sbh   = stage ? S_W2F  : S_W1F;
            const int sbl   = stage ? S_W2LO : S_W1LO;
            const int sbias = stage ? S_B2   : S_B1;

            unsigned Ah[2][8][4], Al[2][8][4];
            #pragma unroll
            for (int mt = 0; mt < 2; mt++)
                #pragma unroll
                for (int ks = 0; ks < 8; ks++)
                    #pragma unroll
                    for (int q = 0; q < 4; q++) {
                        int el = 32*wid + 16*mt + g + (q & 1) * 8;
                        int kk = 8*ks + tig + (q >> 1) * 4;
                        float v = act[kk * ACT_S + el];
                        unsigned hu = tf32_of(v);
                        Ah[mt][ks][q] = hu;
                        Al[mt][ks][q] = tf32_of(v - __uint_as_float(hu));
                    }
            __syncwarp();   // all gathers done before in-place writes

            #pragma unroll 1
            for (int nt = 0; nt < 8; nt++) {
                float bv0 = s[sbias + 8*nt + 2*tig];
                float bv1 = s[sbias + 8*nt + 2*tig + 1];
                float d[2][4] = {{bv0,bv1,bv0,bv1},{bv0,bv1,bv0,bv1}};
                #pragma unroll
                for (int ks = 0; ks < 8; ks++) {
                    int fidx = (ks * 8 + nt) * 32 + lane;
                    u64 bh = *(const u64*)(s + sbh + fidx * 2);
                    float bh0, bh1; unpack2(bh, bh0, bh1);
                    unsigned blo = *(const unsigned*)(s + sbl + fidx);
                    unsigned b0h = __float_as_uint(bh0), b1h = __float_as_uint(bh1);
                    unsigned b0l = blo << 16, b1l = blo & 0xffff0000u;
                    #pragma unroll
                    for (int mt = 0; mt < 2; mt++) {
                        mma8(d[mt], Ah[mt][ks], b0h, b1h);
                        mma8(d[mt], Al[mt][ks], b0h, b1h);
                        mma8(d[mt], Ah[mt][ks], b0l, b1l);
                    }
                }
                int r0 = (8*nt + 2*tig) * ACT_S, r1 = r0 + ACT_S;
                #pragma unroll
                for (int mt = 0; mt < 2; mt++) {
                    int e0 = 32*wid + 16*mt + g, e1 = e0 + 8;
                    act[r0 + e0] = fmaxf(d[mt][0], 0.f);
                    act[r1 + e0] = fmaxf(d[mt][1], 0.f);
                    act[r0 + e1] = fmaxf(d[mt][2], 0.f);
                    act[r1 + e1] = fmaxf(d[mt][3], 0.f);
                }
            }
            __syncwarp();
        }
        // act rows 0..63 hold h2

        { // stage src node feats (row per edge)
            const float4* nf = (const float4*)(node_feats + (size_t)edge_index[ee] * NODE_IN);
            float4* xr = (float4*)(s + S_XS + tid * XS_S);
            xr[0] = nf[0]; xr[1] = nf[1]; xr[2] = nf[2]; xr[3] = nf[3];
        }
        __syncwarp();

        // ---- lw GEMM fused with x-contraction (proven) ----
        unsigned Ah[2][8][4], Al[2][8][4];
        #pragma unroll
        for (int mt = 0; mt < 2; mt++)
            #pragma unroll
            for (int ks = 0; ks < 8; ks++)
                #pragma unroll
                for (int q = 0; q < 4; q++) {
                    int el = 32*wid + 16*mt + g + (q & 1) * 8;
                    int kk = 8*ks + tig + (q >> 1) * 4;
                    float v = act[kk * ACT_S + el];
                    unsigned hu = tf32_of(v);
                    Ah[mt][ks][q] = hu;
                    Al[mt][ks][q] = tf32_of(v - __uint_as_float(hu));
                }

        u64 msg[4][2];
        #pragma unroll
        for (int j = 0; j < 4; j++) { msg[j][0] = 0ull; msg[j][1] = 0ull; }
        #pragma unroll 1
        for (int i = 0; i < NODE_IN; i++) {
            u64 lb0 = *(const u64*)(s + S_LB + i*OUT + 2*tig);
            u64 lb1 = *(const u64*)(s + S_LB + i*OUT + 2*tig + 8);
            #pragma unroll
            for (int j = 0; j < 4; j++) {
                int el = 32*wid + (j >> 1) * 16 + (j & 1) * 8 + g;
                u64 xv = pack2(s[S_XS + el * XS_S + i]);
                msg[j][0] = ffma2(xv, lb0, msg[j][0]);
                msg[j][1] = ffma2(xv, lb1, msg[j][1]);
            }
        }

        #pragma unroll 1
        for (int nt = 0; nt < 32; nt++) {
            float d[2][4] = {{0,0,0,0},{0,0,0,0}};
            #pragma unroll
            for (int ks = 0; ks < 8; ks++) {
                int fidx = (ks * 32 + nt) * 32 + lane;
                u64 bh = *(const u64*)(s + S_LWHI + fidx * 2);
                float bh0, bh1; unpack2(bh, bh0, bh1);
                unsigned blo = *(const unsigned*)(s + S_LWLO + fidx);
                unsigned b0h = __float_as_uint(bh0), b1h = __float_as_uint(bh1);
                unsigned b0l = blo << 16, b1l = blo & 0xffff0000u;
                #pragma unroll
                for (int mt = 0; mt < 2; mt++) {
                    mma8(d[mt], Ah[mt][ks], b0h, b1h);
                    mma8(d[mt], Al[mt][ks], b0h, b1h);
                    mma8(d[mt], Ah[mt][ks], b0l, b1l);
                }
            }
            int i = nt >> 1, par = nt & 1;
            #pragma unroll
            for (int mt = 0; mt < 2; mt++) {
                int e0 = 32*wid + 16*mt + g, e1 = e0 + 8;
                msg[2*mt+0][par] = ffma2(pack2(s[S_XS + e0*XS_S + i]), packf(d[mt][0], d[mt][1]), msg[2*mt+0][par]);
                msg[2*mt+1][par] = ffma2(pack2(s[S_XS + e1*XS_S + i]), packf(d[mt][2], d[mt][3]), msg[2*mt+1][par]);
            }
        }

        // scatter max: branch-free ordered-int RED.MAX
        #pragma unroll
        for (int j = 0; j < 4; j++) {
            int el = 32*wid + (j >> 1) * 16 + (j & 1) * 8 + g;
            int eg = tile * T + el;
            if (eg < E) {
                int* slot = &g_agg[(size_t)edge_index[E + eg] * OUT];
                float m0, m1, m2, m3;
                unpack2(msg[j][0], m0, m1);
                unpack2(msg[j][1], m2, m3);
                atomicMax(slot + 2*tig + 0, ford(m0));
                atomicMax(slot + 2*tig + 1, ford(m1));
                atomicMax(slot + 2*tig + 8, ford(m2));
                atomicMax(slot + 2*tig + 9, ford(m3));
            }
        }
        __syncwarp();
    }
}

__global__ __launch_bounds__(256)
void node_kernel(const float* __restrict__ node_feats,
                 const float* __restrict__ root_w,
                 const float* __restrict__ bias,
                 float* __restrict__ out, int N)
{
    __shared__ float rw[NODE_IN * OUT];
    __shared__ float bs[OUT];
    int tid = threadIdx.x;
    if (tid < NODE_IN * OUT) rw[tid] = root_w[tid];
    if (tid < OUT) bs[tid] = bias[tid];
    __syncthreads();

    int n = blockIdx.x * 256 + tid;
    if (n >= N) return;

    float xi[NODE_IN];
    {
        const float4* nf = (const float4*)(node_feats + (size_t)n * NODE_IN);
        float4 a = nf[0], b = nf[1], c = nf[2], d4 = nf[3];
        xi[0]=a.x;  xi[1]=a.y;  xi[2]=a.z;  xi[3]=a.w;
        xi[4]=b.x;  xi[5]=b.y;  xi[6]=b.z;  xi[7]=b.w;
        xi[8]=c.x;  xi[9]=c.y;  xi[10]=c.z; xi[11]=c.w;
        xi[12]=d4.x; xi[13]=d4.y; xi[14]=d4.z; xi[15]=d4.w;
    }

    float o[OUT];
    #pragma unroll
    for (int j = 0; j < OUT; j++) o[j] = bs[j];
    #pragma unroll
    for (int i = 0; i < NODE_IN; i++) {
        float xv = xi[i];
        #pragma unroll
        for (int j = 0; j < OUT; j++) o[j] = fmaf(xv, rw[i*OUT + j], o[j]);
    }

    #pragma unroll
    for (int j = 0; j < OUT; j++) {
        int a = g_agg[(size_t)n * OUT + j];
        float av;
        if (a == (int)0x80000000) av = 0.f;
        else av = __int_as_float(a >= 0 ? a : (a ^ 0x7fffffff));
        o[j] += av;
    }

    float4* ov = (float4*)(out + (size_t)n * OUT);
    ov[0] = make_float4(o[0],  o[1],  o[2],  o[3]);
    ov[1] = make_float4(o[4],  o[5],  o[6],  o[7]);
    ov[2] = make_float4(o[8],  o[9],  o[10], o[11]);
    ov[3] = make_float4(o[12], o[13], o[14], o[15]);
}

extern "C" void kernel_launch(void* const* d_in, const int* in_sizes, int n_in,
                              void* d_out, int out_size)
{
    const float* node_feats = (const float*)d_in[0];
    const int*   edge_index = (const int*)  d_in[1];
    const float* edge_feats = (const float*)d_in[2];
    const float* w0 = (const float*)d_in[3];
    const float* b0 = (const float*)d_in[4];
    const float* w1 = (const float*)d_in[5];
    const float* b1 = (const float*)d_in[6];
    const float* w2 = (const float*)d_in[7];
    const float* b2 = (const float*)d_in[8];
    const float* lw = (const float*)d_in[9];
    const float* lb = (const float*)d_in[10];
    const float* root_w = (const float*)d_in[11];
    const float* bias   = (const float*)d_in[12];

    int E = in_sizes[1] / 2;
    int N = in_sizes[0] / NODE_IN;

    cudaFuncSetAttribute(edge_kernel, cudaFuncAttributeMaxDynamicSharedMemorySize, SMEM_BYTES);

    init_agg_kernel<<<(N * OUT + 255) / 256, 256>>>(N * OUT);
    prep_lw_kernel<<<(WIDTH * NODE_IN * OUT + 255) / 256, 256>>>(lw);
    prep_w1_kernel<<<(WIDTH * WIDTH + 255) / 256, 256>>>(w1);
    prep_w2_kernel<<<(WIDTH * WIDTH + 255) / 256, 256>>>(w2);

    int ntiles = (E + T - 1) / T;
    int grid = ntiles < NBLK ? ntiles : NBLK;
    edge_kernel<<<grid, T, SMEM_BYTES>>>(
        node_feats, edge_index, edge_feats, w0, b0, b1, b2, lb, E);

    node_kernel<<<(N + 255) / 256, 256>>>(node_feats, root_w, bias, (float*)d_out, N);
}

// round 17
// speedup vs baseline: 1.8697x; 1.0480x over previous
#include <cuda_runtime.h>
#include <cuda_bf16.h>
#include <stdint.h>

#define EDGE_IN 19
#define WIDTH   64
#define NODE_IN 16
#define OUT     16
#define N_NODES_MAX 50000
#define T 224        // threads per block = edges per tile (7 warps)
#define ACT_S 232    // ==8 mod 32 -> conflict-free A-frag gathers
#define XS_S 16
#define NBLK 148

// ---- shared memory layout (float offsets, all 16B-aligned) ----
#define S_B0    0        // 64
#define S_B1    64       // 64
#define S_B2    128      // 64
#define S_LB    192      // 256
#define S_W0F   448      // 1536 (K=24 padded, tf32-hi, B-frag order)
#define S_W0LO  1984     // 768  (1536 bf16)
#define S_W1F   2752     // 4096
#define S_W1LO  6848     // 2048
#define S_W2F   8896     // 4096
#define S_W2LO  12992    // 2048
#define S_LWHI  15040    // 16384
#define S_LWLO  31424    // 8192
#define S_XS    39616    // 224*16 = 3584
#define S_ACT   43200    // 64*232 = 14848
#define SMEM_FLOATS 58048
#define SMEM_BYTES (SMEM_FLOATS*4)   // 232192 B (cap 232448)

typedef unsigned long long u64;

__device__ __forceinline__ u64 ffma2(u64 a, u64 b, u64 c) {
    u64 d; asm("fma.rn.f32x2 %0, %1, %2, %3;" : "=l"(d) : "l"(a), "l"(b), "l"(c)); return d;
}
__device__ __forceinline__ u64 pack2(float x) {
    u64 r; asm("mov.b64 %0, {%1, %1};" : "=l"(r) : "f"(x)); return r;
}
__device__ __forceinline__ u64 packf(float lo, float hi) {
    u64 r; asm("mov.b64 %0, {%1, %2};" : "=l"(r) : "f"(lo), "f"(hi)); return r;
}
__device__ __forceinline__ void unpack2(u64 v, float& lo, float& hi) {
    asm("mov.b64 {%0, %1}, %2;" : "=f"(lo), "=f"(hi) : "l"(v));
}
__device__ __forceinline__ int ford(float f) {
    int b = __float_as_int(f); return b >= 0 ? b : (b ^ 0x7fffffff);
}
__device__ __forceinline__ unsigned tf32_of(float x) {
    unsigned r; asm("cvt.rna.tf32.f32 %0, %1;" : "=r"(r) : "f"(x)); return r;
}
__device__ __forceinline__ void mma8(float* d, const unsigned* a, unsigned b0, unsigned b1) {
    asm volatile("mma.sync.aligned.m16n8k8.row.col.f32.tf32.tf32.f32 "
        "{%0,%1,%2,%3}, {%4,%5,%6,%7}, {%8,%9}, {%0,%1,%2,%3};"
        : "+f"(d[0]), "+f"(d[1]), "+f"(d[2]), "+f"(d[3])
        : "r"(a[0]), "r"(a[1]), "r"(a[2]), "r"(a[3]), "r"(b0), "r"(b1));
}

__device__ int g_agg[N_NODES_MAX * OUT];
__device__ float         g_lwhi[WIDTH * NODE_IN * OUT];
__device__ __nv_bfloat16 g_lwlo[WIDTH * NODE_IN * OUT];
__device__ float         g_w0f[24 * WIDTH];
__device__ __nv_bfloat16 g_w0lo[24 * WIDTH];
__device__ float         g_w1f[WIDTH * WIDTH];
__device__ __nv_bfloat16 g_w1lo[WIDTH * WIDTH];
__device__ float         g_w2f[WIDTH * WIDTH];
__device__ __nv_bfloat16 g_w2lo[WIDTH * WIDTH];

__global__ void init_agg_kernel(int n) {
    int i = blockIdx.x * blockDim.x + threadIdx.x;
    if (i < n) g_agg[i] = (int)0x80000000;
}

// All prep kernels write __device__ globals BY NAME (host-passed device-global
// pointers are shadow symbols -> wild writes; learned R7-R16).
__global__ void prep_lw_kernel(const float* __restrict__ lw) {
    int idx = blockIdx.x * 256 + threadIdx.x;
    if (idx >= WIDTH * NODE_IN * OUT) return;
    int k = idx >> 8, nn = idx & 255;
    float w = lw[idx];
    float hif = __uint_as_float(tf32_of(w));
    int pos = (((k >> 3) * 32 + (nn >> 3)) * 32 + (nn & 7) * 4 + (k & 3)) * 2 + ((k & 7) >> 2);
    g_lwhi[pos] = hif;
    g_lwlo[pos] = __float2bfloat16(w - hif);
}

__global__ void prep_w0_kernel(const float* __restrict__ w) {   // K=19 pad to 24
    int idx = blockIdx.x * 256 + threadIdx.x;
    if (idx >= 24 * WIDTH) return;
    int k = idx >> 6, nn = idx & 63;
    float v = (k < EDGE_IN) ? w[k * WIDTH + nn] : 0.f;
    float hif = __uint_as_float(tf32_of(v));
    int pos = (((k >> 3) * 8 + (nn >> 3)) * 32 + (nn & 7) * 4 + (k & 3)) * 2 + ((k & 7) >> 2);
    g_w0f[pos] = hif;
    g_w0lo[pos] = __float2bfloat16(v - hif);
}

__global__ void prep_w1_kernel(const float* __restrict__ w) {
    int idx = blockIdx.x * 256 + threadIdx.x;
    if (idx >= WIDTH * WIDTH) return;
    int k = idx >> 6, nn = idx & 63;
    float v = w[idx];
    float hif = __uint_as_float(tf32_of(v));
    int pos = (((k >> 3) * 8 + (nn >> 3)) * 32 + (nn & 7) * 4 + (k & 3)) * 2 + ((k & 7) >> 2);
    g_w1f[pos] = hif;
    g_w1lo[pos] = __float2bfloat16(v - hif);
}

__global__ void prep_w2_kernel(const float* __restrict__ w) {
    int idx = blockIdx.x * 256 + threadIdx.x;
    if (idx >= WIDTH * WIDTH) return;
    int k = idx >> 6, nn = idx & 63;
    float v = w[idx];
    float hif = __uint_as_float(tf32_of(v));
    int pos = (((k >> 3) * 8 + (nn >> 3)) * 32 + (nn & 7) * 4 + (k & 3)) * 2 + ((k & 7) >> 2);
    g_w2f[pos] = hif;
    g_w2lo[pos] = __float2bfloat16(v - hif);
}

__global__ __launch_bounds__(T, 1)
void edge_kernel(const float* __restrict__ node_feats,
                 const int*   __restrict__ edge_index,
                 const float* __restrict__ edge_feats,
                 const float* __restrict__ b0, const float* __restrict__ b1,
                 const float* __restrict__ b2, const float* __restrict__ lb, int E)
{
    extern __shared__ float s[];
    const int tid = threadIdx.x;
    const int lane = tid & 31, wid = tid >> 5;
    const int g = lane >> 2, tig = lane & 3;

    { // cooperative constant load (once per persistent block)
        float4* d = (float4*)s; const float4* v;
        v = (const float4*)b0;      for (int i = tid; i < 16;   i += T) d[S_B0/4 + i]   = v[i];
        v = (const float4*)b1;      for (int i = tid; i < 16;   i += T) d[S_B1/4 + i]   = v[i];
        v = (const float4*)b2;      for (int i = tid; i < 16;   i += T) d[S_B2/4 + i]   = v[i];
        v = (const float4*)lb;      for (int i = tid; i < 64;   i += T) d[S_LB/4 + i]   = v[i];
        v = (const float4*)g_w0f;   for (int i = tid; i < 384;  i += T) d[S_W0F/4 + i]  = v[i];
        v = (const float4*)g_w0lo;  for (int i = tid; i < 192;  i += T) d[S_W0LO/4 + i] = v[i];
        v = (const float4*)g_w1f;   for (int i = tid; i < 1024; i += T) d[S_W1F/4 + i]  = v[i];
        v = (const float4*)g_w1lo;  for (int i = tid; i < 512;  i += T) d[S_W1LO/4 + i] = v[i];
        v = (const float4*)g_w2f;   for (int i = tid; i < 1024; i += T) d[S_W2F/4 + i]  = v[i];
        v = (const float4*)g_w2lo;  for (int i = tid; i < 512;  i += T) d[S_W2LO/4 + i] = v[i];
        v = (const float4*)g_lwhi;  for (int i = tid; i < 4096; i += T) d[S_LWHI/4 + i] = v[i];
        v = (const float4*)g_lwlo;  for (int i = tid; i < 2048; i += T) d[S_LWLO/4 + i] = v[i];
    }
    __syncthreads();

    float* act = s + S_ACT;
    const int ntiles = (E + T - 1) / T;

    // MMA MLP layer, nt-PAIRED for 4 independent accumulator chains.
    // Gather-all-first, __syncwarp, then in-place act writes (proven safe).
    #define MMALAYER(KSN, SBH, SBL, SBIAS)                                           \
    {                                                                                \
        unsigned Ah[2][KSN][4], Al[2][KSN][4];                                       \
        _Pragma("unroll")                                                            \
        for (int mt = 0; mt < 2; mt++)                                               \
            _Pragma("unroll")                                                        \
            for (int ks = 0; ks < KSN; ks++)                                         \
                _Pragma("unroll")                                                    \
                for (int q = 0; q < 4; q++) {                                        \
                    int el = 32*wid + 16*mt + g + (q & 1) * 8;                       \
                    int kk = 8*ks + tig + (q >> 1) * 4;                              \
                    float vv = act[kk * ACT_S + el];                                 \
                    unsigned hu = tf32_of(vv);                                       \
                    Ah[mt][ks][q] = hu;                                              \
                    Al[mt][ks][q] = tf32_of(vv - __uint_as_float(hu));               \
                }                                                                    \
        __syncwarp();                                                                \
        _Pragma("unroll 1")                                                          \
        for (int nt2 = 0; nt2 < 4; nt2++) {                                          \
            float d[2][2][4];  /* [par][mt] */                                       \
            _Pragma("unroll")                                                        \
            for (int p = 0; p < 2; p++) {                                            \
                float bv0 = s[(SBIAS) + 8*(2*nt2+p) + 2*tig];                        \
                float bv1 = s[(SBIAS) + 8*(2*nt2+p) + 2*tig + 1];                    \
                d[p][0][0]=bv0; d[p][0][1]=bv1; d[p][0][2]=bv0; d[p][0][3]=bv1;      \
                d[p][1][0]=bv0; d[p][1][1]=bv1; d[p][1][2]=bv0; d[p][1][3]=bv1;      \
            }                                                                        \
            _Pragma("unroll")                                                        \
            for (int ks = 0; ks < KSN; ks++)                                         \
                _Pragma("unroll")                                                    \
                for (int p = 0; p < 2; p++) {                                        \
                    int fidx = (ks * 8 + 2*nt2 + p) * 32 + lane;                     \
                    u64 bh = *(const u64*)(s + (SBH) + fidx * 2);                    \
                    float bh0, bh1; unpack2(bh, bh0, bh1);                           \
                    unsigned blo = *(const unsigned*)(s + (SBL) + fidx);             \
                    unsigned b0h = __float_as_uint(bh0), b1h = __float_as_uint(bh1); \
                    unsigned b0l = blo << 16, b1l = blo & 0xffff0000u;               \
                    _Pragma("unroll")                                                \
                    for (int mt = 0; mt < 2; mt++) {                                 \
                        mma8(d[p][mt], Ah[mt][ks], b0h, b1h);                        \
                        mma8(d[p][mt], Al[mt][ks], b0h, b1h);                        \
                        mma8(d[p][mt], Ah[mt][ks], b0l, b1l);                        \
                    }                                                                \
                }                                                                    \
            _Pragma("unroll")                                                        \
            for (int p = 0; p < 2; p++) {                                            \
                int r0 = (8*(2*nt2+p) + 2*tig) * ACT_S, r1 = r0 + ACT_S;             \
                _Pragma("unroll")                                                    \
                for (int mt = 0; mt < 2; mt++) {                                     \
                    int e0 = 32*wid + 16*mt + g, e1 = e0 + 8;                        \
                    act[r0 + e0] = fmaxf(d[p][mt][0], 0.f);                          \
                    act[r1 + e0] = fmaxf(d[p][mt][1], 0.f);                          \
                    act[r0 + e1] = fmaxf(d[p][mt][2], 0.f);                          \
                    act[r1 + e1] = fmaxf(d[p][mt][3], 0.f);                          \
                }                                                                    \
            }                                                                        \
        }                                                                            \
        __syncwarp();                                                                \
    }

    for (int tile = blockIdx.x; tile < ntiles; tile += gridDim.x) {
        int e = tile * T + tid;
        int ee = (e < E) ? e : (E - 1);

        // stage edge feats rows 0..18, zero-pad rows 19..23 (K=24 for layer0)
        #pragma unroll
        for (int k = 0; k < EDGE_IN; k++)
            act[k * ACT_S + tid] = edge_feats[(size_t)ee * EDGE_IN + k];
        #pragma unroll
        for (int k = EDGE_IN; k < 24; k++)
            act[k * ACT_S + tid] = 0.f;
        __syncwarp();

        MMALAYER(3, S_W0F, S_W0LO, S_B0)   // layer0 (19pad24 -> 64)
        // layers 1 & 2 share ONE instantiation via stage loop
        #pragma unroll 1
        for (int stage = 0; stage < 2; stage++) {
            const int sbh   = stage ? S_W2F  : S_W1F;
            const int sbl   = stage ? S_W2LO : S_W1LO;
            const int sbias = stage ? S_B2   : S_B1;
            MMALAYER(8, sbh, sbl, sbias)
        }
        // act rows 0..63 hold h2

        { // stage src node feats (row per edge)
            const float4* nf = (const float4*)(node_feats + (size_t)edge_index[ee] * NODE_IN);
            float4* xr = (float4*)(s + S_XS + tid * XS_S);
            xr[0] = nf[0]; xr[1] = nf[1]; xr[2] = nf[2]; xr[3] = nf[3];
        }
        __syncwarp();

        // ---- lw GEMM fused with x-contraction, nt-PAIRED ----
        unsigned Ah[2][8][4], Al[2][8][4];
        #pragma unroll
        for (int mt = 0; mt < 2; mt++)
            #pragma unroll
            for (int ks = 0; ks < 8; ks++)
                #pragma unroll
                for (int q = 0; q < 4; q++) {
                    int el = 32*wid + 16*mt + g + (q & 1) * 8;
                    int kk = 8*ks + tig + (q >> 1) * 4;
                    float v = act[kk * ACT_S + el];
                    unsigned hu = tf32_of(v);
                    Ah[mt][ks][q] = hu;
                    Al[mt][ks][q] = tf32_of(v - __uint_as_float(hu));
                }

        u64 msg[4][2];
        #pragma unroll
        for (int j = 0; j < 4; j++) { msg[j][0] = 0ull; msg[j][1] = 0ull; }
        #pragma unroll 1
        for (int i = 0; i < NODE_IN; i++) {
            u64 lb0 = *(const u64*)(s + S_LB + i*OUT + 2*tig);
            u64 lb1 = *(const u64*)(s + S_LB + i*OUT + 2*tig + 8);
            #pragma unroll
            for (int j = 0; j < 4; j++) {
                int el = 32*wid + (j >> 1) * 16 + (j & 1) * 8 + g;
                u64 xv = pack2(s[S_XS + el * XS_S + i]);
                msg[j][0] = ffma2(xv, lb0, msg[j][0]);
                msg[j][1] = ffma2(xv, lb1, msg[j][1]);
            }
        }

        #pragma unroll 1
        for (int i = 0; i < 16; i++) {      // i = nt>>1; pair covers par=0,1
            float d[2][2][4];               // [par][mt]
            #pragma unroll
            for (int p = 0; p < 2; p++)
                #pragma unroll
                for (int mt = 0; mt < 2; mt++)
                    #pragma unroll
                    for (int q = 0; q < 4; q++) d[p][mt][q] = 0.f;
            #pragma unroll
            for (int ks = 0; ks < 8; ks++)
                #pragma unroll
                for (int p = 0; p < 2; p++) {
                    int fidx = (ks * 32 + 2*i + p) * 32 + lane;
                    u64 bh = *(const u64*)(s + S_LWHI + fidx * 2);
                    float bh0, bh1; unpack2(bh, bh0, bh1);
                    unsigned blo = *(const unsigned*)(s + S_LWLO + fidx);
                    unsigned b0h = __float_as_uint(bh0), b1h = __float_as_uint(bh1);
                    unsigned b0l = blo << 16, b1l = blo & 0xffff0000u;
                    #pragma unroll
                    for (int mt = 0; mt < 2; mt++) {
                        mma8(d[p][mt], Ah[mt][ks], b0h, b1h);
                        mma8(d[p][mt], Al[mt][ks], b0h, b1h);
                        mma8(d[p][mt], Ah[mt][ks], b0l, b1l);
                    }
                }
            #pragma unroll
            for (int mt = 0; mt < 2; mt++) {
                int e0 = 32*wid + 16*mt + g, e1 = e0 + 8;
                u64 x0 = pack2(s[S_XS + e0*XS_S + i]);
                u64 x1 = pack2(s[S_XS + e1*XS_S + i]);
                #pragma unroll
                for (int p = 0; p < 2; p++) {
                    msg[2*mt+0][p] = ffma2(x0, packf(d[p][mt][0], d[p][mt][1]), msg[2*mt+0][p]);
                    msg[2*mt+1][p] = ffma2(x1, packf(d[p][mt][2], d[p][mt][3]), msg[2*mt+1][p]);
                }
            }
        }

        // scatter max: branch-free ordered-int RED.MAX
        #pragma unroll
        for (int j = 0; j < 4; j++) {
            int el = 32*wid + (j >> 1) * 16 + (j & 1) * 8 + g;
            int eg = tile * T + el;
            if (eg < E) {
                int* slot = &g_agg[(size_t)edge_index[E + eg] * OUT];
                float m0, m1, m2, m3;
                unpack2(msg[j][0], m0, m1);
                unpack2(msg[j][1], m2, m3);
                atomicMax(slot + 2*tig + 0, ford(m0));
                atomicMax(slot + 2*tig + 1, ford(m1));
                atomicMax(slot + 2*tig + 8, ford(m2));
                atomicMax(slot + 2*tig + 9, ford(m3));
            }
        }
        __syncwarp();
    }
    #undef MMALAYER
}

__global__ __launch_bounds__(256)
void node_kernel(const float* __restrict__ node_feats,
                 const float* __restrict__ root_w,
                 const float* __restrict__ bias,
                 float* __restrict__ out, int N)
{
    __shared__ float rw[NODE_IN * OUT];
    __shared__ float bs[OUT];
    int tid = threadIdx.x;
    if (tid < NODE_IN * OUT) rw[tid] = root_w[tid];
    if (tid < OUT) bs[tid] = bias[tid];
    __syncthreads();

    int n = blockIdx.x * 256 + tid;
    if (n >= N) return;

    float xi[NODE_IN];
    {
        const float4* nf = (const float4*)(node_feats + (size_t)n * NODE_IN);
        float4 a = nf[0], b = nf[1], c = nf[2], d4 = nf[3];
        xi[0]=a.x;  xi[1]=a.y;  xi[2]=a.z;  xi[3]=a.w;
        xi[4]=b.x;  xi[5]=b.y;  xi[6]=b.z;  xi[7]=b.w;
        xi[8]=c.x;  xi[9]=c.y;  xi[10]=c.z; xi[11]=c.w;
        xi[12]=d4.x; xi[13]=d4.y; xi[14]=d4.z; xi[15]=d4.w;
    }

    float o[OUT];
    #pragma unroll
    for (int j = 0; j < OUT; j++) o[j] = bs[j];
    #pragma unroll
    for (int i = 0; i < NODE_IN; i++) {
        float xv = xi[i];
        #pragma unroll
        for (int j = 0; j < OUT; j++) o[j] = fmaf(xv, rw[i*OUT + j], o[j]);
    }

    #pragma unroll
    for (int j = 0; j < OUT; j++) {
        int a = g_agg[(size_t)n * OUT + j];
        float av;
        if (a == (int)0x80000000) av = 0.f;
        else av = __int_as_float(a >= 0 ? a : (a ^ 0x7fffffff));
        o[j] += av;
    }

    float4* ov = (float4*)(out + (size_t)n * OUT);
    ov[0] = make_float4(o[0],  o[1],  o[2],  o[3]);
    ov[1] = make_float4(o[4],  o[5],  o[6],  o[7]);
    ov[2] = make_float4(o[8],  o[9],  o[10], o[11]);
    ov[3] = make_float4(o[12], o[13], o[14], o[15]);
}

extern "C" void kernel_launch(void* const* d_in, const int* in_sizes, int n_in,
                              void* d_out, int out_size)
{
    const float* node_feats = (const float*)d_in[0];
    const int*   edge_index = (const int*)  d_in[1];
    const float* edge_feats = (const float*)d_in[2];
    const float* w0 = (const float*)d_in[3];
    const float* b0 = (const float*)d_in[4];
    const float* w1 = (const float*)d_in[5];
    const float* b1 = (const float*)d_in[6];
    const float* w2 = (const float*)d_in[7];
    const float* b2 = (const float*)d_in[8];
    const float* lw = (const float*)d_in[9];
    const float* lb = (const float*)d_in[10];
    const float* root_w = (const float*)d_in[11];
    const float* bias   = (const float*)d_in[12];

    int E = in_sizes[1] / 2;
    int N = in_sizes[0] / NODE_IN;

    cudaFuncSetAttribute(edge_kernel, cudaFuncAttributeMaxDynamicSharedMemorySize, SMEM_BYTES);

    init_agg_kernel<<<(N * OUT + 255) / 256, 256>>>(N * OUT);
    prep_lw_kernel<<<(WIDTH * NODE_IN * OUT + 255) / 256, 256>>>(lw);
    prep_w0_kernel<<<(24 * WIDTH + 255) / 256, 256>>>(w0);
    prep_w1_kernel<<<(WIDTH * WIDTH + 255) / 256, 256>>>(w1);
    prep_w2_kernel<<<(WIDTH * WIDTH + 255) / 256, 256>>>(w2);

    int ntiles = (E + T - 1) / T;
    int grid = ntiles < NBLK ? ntiles : NBLK;
    edge_kernel<<<grid, T, SMEM_BYTES>>>(
        node_feats, edge_index, edge_feats, b0, b1, b2, lb, E);

    node_kernel<<<(N + 255) / 256, 256>>>(node_feats, root_w, bias, (float*)d_out, N);
}